// round 11
// baseline (speedup 1.0000x reference)
#include <cuda_runtime.h>
#include <math.h>
#include <stdint.h>

// ---------------- problem constants ----------------
#define BATCH   2
#define S_LEN   2048
#define NROWS   (BATCH * S_LEN)     // 4096
#define DIM_    1024
#define NH      8
#define SM_SCALE 0.08838834764831845f   // 1/sqrt(128)
#define CQKV_N  384                      // 128 (cq) + 192 (ckv_kr) + 64 pad
#define KD2     192                      // absorbed K dim: 128 ckv + 64 rope
#define QN2     1536                     // 8 heads * 192

// ---------------- scratch ----------------
__device__ float g_cq   [(size_t)NROWS * 128];
__device__ float g_ks   [(size_t)NROWS * KD2];               // [b,s,192] head-shared
__device__ float g_qs   [(size_t)BATCH * NH * S_LEN * KD2];  // [b,h,s,192]
__device__ float g_attn [(size_t)NROWS * 1024];              // P@ckv concat heads
__device__ float g_x32  [(size_t)NROWS * DIM_];
__device__ float g_w13  [(size_t)DIM_ * CQKV_N];
__device__ float g_b13  [CQKV_N];
__device__ float g_w2   [(size_t)128 * 1024];
__device__ float g_w4   [(size_t)128 * 2560];
__device__ float g_w5   [(size_t)2048 * DIM_];
__device__ float g_wqn  [(size_t)128 * QN2];                 // absorbed q weights
__device__ float g_bqn  [QN2];
__device__ float g_weff [(size_t)1024 * 1024];               // W_uv @ W_o
__device__ float g_beff [1024];

// ---------------- helpers ----------------
__device__ __forceinline__ float to_tf32(float x) {
    uint32_t u;
    asm("cvt.rna.tf32.f32 %0, %1;" : "=r"(u) : "f"(x));
    return __uint_as_float(u);
}

__device__ __forceinline__ void mma_tf32(float* c, uint32_t a0, uint32_t a1,
                                         uint32_t a2, uint32_t a3,
                                         uint32_t b0, uint32_t b1) {
    asm volatile(
        "mma.sync.aligned.m16n8k8.row.col.f32.tf32.tf32.f32 "
        "{%0,%1,%2,%3}, {%4,%5,%6,%7}, {%8,%9}, {%0,%1,%2,%3};"
        : "+f"(c[0]), "+f"(c[1]), "+f"(c[2]), "+f"(c[3])
        : "r"(a0), "r"(a1), "r"(a2), "r"(a3), "r"(b0), "r"(b1));
}

__device__ __forceinline__ void cp_async16(void* smem_ptr, const void* gptr) {
    uint32_t s = (uint32_t)__cvta_generic_to_shared(smem_ptr);
    asm volatile("cp.async.cg.shared.global [%0], [%1], 16;" :: "r"(s), "l"(gptr));
}
#define CP_COMMIT() asm volatile("cp.async.commit_group;")
#define CP_WAIT0()  asm volatile("cp.async.wait_group 0;")
#define CP_WAIT1()  asm volatile("cp.async.wait_group 1;")

// ---------------- tf32 rounding / w13 packing ----------------
#define RA_X   1048576
#define RA_W2  (RA_X  + 32768)
#define RA_W4  (RA_W2 + 81920)
#define RA_W5  (RA_W4 + 524288)
#define RA_W13 (RA_W5 + 98304)
#define RA_B13 (RA_W13 + 96)
#define RA_TOTAL RA_B13

__global__ __launch_bounds__(256)
void round_all_kernel(const float* __restrict__ x,    float* __restrict__ ox,
                      const float* __restrict__ w2i,  float* __restrict__ w2o,
                      const float* __restrict__ w4i,  float* __restrict__ w4o,
                      const float* __restrict__ w5i,  float* __restrict__ w5o,
                      const float* __restrict__ w1i,  const float* __restrict__ w3i,
                      float* __restrict__ w13o,
                      const float* __restrict__ b1i,  const float* __restrict__ b3i,
                      float* __restrict__ b13o)
{
    int i = blockIdx.x * 256 + threadIdx.x;
    if (i >= RA_TOTAL) return;
    float4 v;
    float4* dst;
    if (i < RA_X)       { v = ((const float4*)x)[i];             dst = (float4*)ox  + i; }
    else if (i < RA_W2) { int o = i - RA_X;  v = ((const float4*)w2i)[o]; dst = (float4*)w2o + o; }
    else if (i < RA_W4) { int o = i - RA_W2; v = ((const float4*)w4i)[o]; dst = (float4*)w4o + o; }
    else if (i < RA_W5) { int o = i - RA_W4; v = ((const float4*)w5i)[o]; dst = (float4*)w5o + o; }
    else if (i < RA_W13) {
        int o = i - RA_W5;
        int k = o / 96, c4 = (o % 96) * 4;
        if (c4 < 128)      v = *(const float4*)(w1i + (size_t)k * 128 + c4);
        else if (c4 < 320) v = *(const float4*)(w3i + (size_t)k * 192 + (c4 - 128));
        else               v = make_float4(0.f, 0.f, 0.f, 0.f);
        dst = (float4*)w13o + o;
    } else {
        int o = i - RA_W13;
        int c4 = o * 4;
        if (c4 < 128)      v = *(const float4*)(b1i + c4);
        else if (c4 < 320) v = *(const float4*)(b3i + (c4 - 128));
        else               v = make_float4(0.f, 0.f, 0.f, 0.f);
        *(float4*)(b13o + c4) = v;
        return;
    }
    v.x = to_tf32(v.x); v.y = to_tf32(v.y);
    v.z = to_tf32(v.z); v.w = to_tf32(v.w);
    *dst = v;
}

// ---------------- absorbed q-weight precompute ----------------
// W_qnew[r, h*192+j]:
//   j<128  : sum_{d<64} w2r[r, h*96+d] * w4r[j, h*64+d]   (tf32-rounded)
//   128-159: w2r[r, h*96+64+(j-128)]
//   160-191: w2r[r, 768+h*32+(j-160)]
__global__ __launch_bounds__(256)
void precompute_wq_kernel(const float* __restrict__ w2r, const float* __restrict__ w4r,
                          const float* __restrict__ b2,  float* __restrict__ wqn,
                          float* __restrict__ bqn)
{
    int idx = blockIdx.x * 256 + threadIdx.x;
    if (idx >= 128 * QN2) return;
    int r = idx / QN2;
    int c = idx % QN2;
    int h = c / KD2;
    int j = c - h * KD2;
    float val, bv = 0.f;
    if (j < 128) {
        float s = 0.f, bs = 0.f;
        const float* w2p = w2r + (size_t)r * 1024 + h * 96;
        const float* w4p = w4r + (size_t)j * 2560 + h * 64;
        const float* b2p = b2 + h * 96;
#pragma unroll 8
        for (int d = 0; d < 64; d++) {
            s  += w2p[d] * w4p[d];
            bs += b2p[d] * w4p[d];
        }
        val = to_tf32(s);
        bv = bs;
    } else if (j < 160) {
        val = w2r[(size_t)r * 1024 + h * 96 + 64 + (j - 128)];
        bv  = b2[h * 96 + 64 + (j - 128)];
    } else {
        val = w2r[(size_t)r * 1024 + 768 + h * 32 + (j - 160)];
        bv  = b2[768 + h * 32 + (j - 160)];
    }
    wqn[(size_t)r * QN2 + c] = val;
    if (r == 0) bqn[c] = bv;
}

// ---------------- b_eff = b_o + b_v @ W_o ----------------
__global__ __launch_bounds__(256)
void precompute_beff_kernel(const float* __restrict__ b45, const float* __restrict__ w_o,
                            const float* __restrict__ b_o, float* __restrict__ beff)
{
    int j = blockIdx.x * 256 + threadIdx.x;
    if (j >= 1024) return;
    float s = b_o[j];
    for (int r = 0; r < 2048; r++)
        s += b45[512 + r] * w_o[(size_t)r * 1024 + j];
    beff[j] = s;
}

// ================= TF32 GEMM core (CTA 128x128, BK=32, 256 thr) =================
#define GBM 128
#define GBN 128
#define GBK 32
#define AS_STRIDE 36
#define BS_STRIDE 136
#define ABUF (GBM * AS_STRIDE)
#define BBUF (GBK * BS_STRIDE)
#define GEMM_SMEM_FLOATS (2 * (ABUF + BBUF))
#define GEMM_SMEM_BYTES  (GEMM_SMEM_FLOATS * 4)

#define GEMM_MAINLOOP(A, lda, B, N, K, m0, n0)                                        \
    float acc[2][8][4];                                                               \
    _Pragma("unroll") for (int mi = 0; mi < 2; mi++)                                  \
    _Pragma("unroll") for (int ni = 0; ni < 8; ni++)                                  \
    _Pragma("unroll") for (int j = 0; j < 4; j++) acc[mi][ni][j] = 0.f;               \
    int nk = (K) / GBK;                                                               \
    auto load_tile = [&](int kt, int bufi) {                                          \
        float* As_ = sm + bufi * (ABUF + BBUF);                                       \
        float* Bs_ = As_ + ABUF;                                                      \
        int k0 = kt * GBK;                                                            \
        _Pragma("unroll") for (int p = 0; p < 4; p++) {                               \
            int idx = tid + p * 256;                                                  \
            int r = idx >> 3, c = (idx & 7) * 4;                                      \
            cp_async16(&As_[r * AS_STRIDE + c], (A) + (size_t)((m0) + r) * (lda) + k0 + c); \
        }                                                                             \
        _Pragma("unroll") for (int p = 0; p < 4; p++) {                               \
            int idx = tid + p * 256;                                                  \
            int r = idx >> 5, c = (idx & 31) * 4;                                     \
            cp_async16(&Bs_[r * BS_STRIDE + c], (B) + (size_t)(k0 + r) * (N) + (n0) + c); \
        }                                                                             \
        CP_COMMIT();                                                                  \
    };                                                                                \
    load_tile(0, 0);                                                                  \
    for (int kt = 0; kt < nk; kt++) {                                                 \
        int bufi = kt & 1;                                                            \
        if (kt + 1 < nk) { load_tile(kt + 1, bufi ^ 1); CP_WAIT1(); }                 \
        else            { CP_WAIT0(); }                                               \
        __syncthreads();                                                              \
        const float* As_ = sm + bufi * (ABUF + BBUF);                                 \
        const float* Bs_ = As_ + ABUF;                                                \
        _Pragma("unroll") for (int k8 = 0; k8 < 4; k8++) {                            \
            int kc = k8 * 8;                                                          \
            uint32_t a[2][4];                                                         \
            _Pragma("unroll") for (int mi = 0; mi < 2; mi++) {                        \
                int row = wm * 32 + mi * 16;                                          \
                a[mi][0] = __float_as_uint(As_[(row + g) * AS_STRIDE + kc + t]);      \
                a[mi][1] = __float_as_uint(As_[(row + g + 8) * AS_STRIDE + kc + t]);  \
                a[mi][2] = __float_as_uint(As_[(row + g) * AS_STRIDE + kc + t + 4]);  \
                a[mi][3] = __float_as_uint(As_[(row + g + 8) * AS_STRIDE + kc + t + 4]); \
            }                                                                         \
            _Pragma("unroll") for (int ni = 0; ni < 8; ni++) {                        \
                int col = wn * 64 + ni * 8 + g;                                       \
                uint32_t b0 = __float_as_uint(Bs_[(kc + t) * BS_STRIDE + col]);       \
                uint32_t b1 = __float_as_uint(Bs_[(kc + t + 4) * BS_STRIDE + col]);   \
                mma_tf32(acc[0][ni], a[0][0], a[0][1], a[0][2], a[0][3], b0, b1);     \
                mma_tf32(acc[1][ni], a[1][0], a[1][1], a[1][2], a[1][3], b0, b1);     \
            }                                                                         \
        }                                                                             \
        __syncthreads();                                                              \
    }

#define GEMM_PREAMBLE                  \
    extern __shared__ float sm[];      \
    int tid  = threadIdx.x;            \
    int wid  = tid >> 5;               \
    int lane = tid & 31;               \
    int wm = wid >> 1;                 \
    int wn = wid & 1;                  \
    int g  = lane >> 2;                \
    int t  = lane & 3;

// ---------------- plain GEMM + bias, fp32 out ----------------
__global__ __launch_bounds__(256, 2)
void gemm_tf32_kernel(const float* __restrict__ A, int lda,
                      const float* __restrict__ B,
                      const float* __restrict__ bias,
                      float* __restrict__ C,
                      int M, int N, int K)
{
    GEMM_PREAMBLE
    int m0 = blockIdx.y * GBM;
    int n0 = blockIdx.x * GBN;
    GEMM_MAINLOOP(A, lda, B, N, K, m0, n0)

#pragma unroll
    for (int ni = 0; ni < 8; ni++) {
        int col = n0 + wn * 64 + ni * 8 + 2 * t;
        float2 bv = *(const float2*)(bias + col);
#pragma unroll
        for (int mi = 0; mi < 2; mi++) {
            int r0 = m0 + wm * 32 + mi * 16 + g;
            float2 v0 = make_float2(acc[mi][ni][0] + bv.x, acc[mi][ni][1] + bv.y);
            float2 v1 = make_float2(acc[mi][ni][2] + bv.x, acc[mi][ni][3] + bv.y);
            *(float2*)(C + (size_t)r0 * N + col) = v0;
            *(float2*)(C + (size_t)(r0 + 8) * N + col) = v1;
        }
    }
}

// ---------------- W_eff batched GEMM: W_eff_h = W_uv_h @ W_o_h ----------------
// blockIdx.z = head; A = w4r[:, 512+h*256 .. +256] (lda 2560); B = w5r rows h*256..
__global__ __launch_bounds__(256, 2)
void gemm_weff_kernel(const float* __restrict__ w4r, const float* __restrict__ w5r,
                      float* __restrict__ weff)
{
    GEMM_PREAMBLE
    int h = blockIdx.z;
    int m0 = 0;
    int n0 = blockIdx.x * GBN;
    const float* A = w4r + 512 + h * 256;
    const float* B = w5r + (size_t)h * 256 * 1024;
    GEMM_MAINLOOP(A, 2560, B, 1024, 256, m0, n0)

#pragma unroll
    for (int ni = 0; ni < 8; ni++) {
        int col = n0 + wn * 64 + ni * 8 + 2 * t;
#pragma unroll
        for (int mi = 0; mi < 2; mi++) {
            int r0 = h * 128 + wm * 32 + mi * 16 + g;
            float2 v0 = make_float2(to_tf32(acc[mi][ni][0]), to_tf32(acc[mi][ni][1]));
            float2 v1 = make_float2(to_tf32(acc[mi][ni][2]), to_tf32(acc[mi][ni][3]));
            *(float2*)(weff + (size_t)r0 * 1024 + col) = v0;
            *(float2*)(weff + (size_t)(r0 + 8) * 1024 + col) = v1;
        }
    }
}

// ---------------- cqkv GEMM (A = pre-rounded x32) ----------------
// tile 0: cq -> rmsnorm(q_norm) -> g_cq [row,128]
// tile 1: ckv -> rmsnorm(kv_norm) -> g_ks[row*192 + 0..127]
// tile 2: k_rope -> RoPE -> g_ks[row*192 + 128..191]
#define STG_STRIDE 129
__global__ __launch_bounds__(256, 2)
void gemm_cqkv_kernel(const float* __restrict__ A,
                      const float* __restrict__ B,
                      const float* __restrict__ bias,
                      const float* __restrict__ wq_norm,
                      const float* __restrict__ wkv_norm,
                      const int* __restrict__ pos,
                      float* __restrict__ cq,
                      float* __restrict__ ks)
{
    GEMM_PREAMBLE
    int m0 = blockIdx.y * GBM;
    int tileN = blockIdx.x;            // 0,1,2
    int n0 = tileN * GBN;
    GEMM_MAINLOOP(A, DIM_, B, CQKV_N, DIM_, m0, n0)

    if (tileN < 2) {
        float* stage = sm;
        float* scl   = sm + 128 * STG_STRIDE;
#pragma unroll
        for (int ni = 0; ni < 8; ni++) {
            int col = wn * 64 + ni * 8 + 2 * t;
            float2 bv = *(const float2*)(bias + n0 + col);
#pragma unroll
            for (int mi = 0; mi < 2; mi++) {
#pragma unroll
                for (int hf = 0; hf < 2; hf++) {
                    int rowl = wm * 32 + mi * 16 + g + hf * 8;
                    stage[rowl * STG_STRIDE + col]     = acc[mi][ni][hf * 2 + 0] + bv.x;
                    stage[rowl * STG_STRIDE + col + 1] = acc[mi][ni][hf * 2 + 1] + bv.y;
                }
            }
        }
        __syncthreads();
        if (tid < 128) {
            const float* rp = stage + tid * STG_STRIDE;
            float ssq = 0.f;
#pragma unroll 16
            for (int c = 0; c < 128; c++) ssq += rp[c] * rp[c];
            scl[tid] = rsqrtf(ssq * (1.f / 128.f) + 1e-8f);
        }
        __syncthreads();
        const float* w = (tileN == 0) ? wq_norm : wkv_norm;
        for (int idx = tid; idx < 128 * 128; idx += 256) {
            int row = idx >> 7, col = idx & 127;
            float v = to_tf32(stage[row * STG_STRIDE + col] * w[col] * scl[row]);
            if (tileN == 0) cq[(size_t)(m0 + row) * 128 + col] = v;
            else            ks[(size_t)(m0 + row) * KD2 + col] = v;
        }
    } else {
        if (wn == 0) {
#pragma unroll
            for (int ni = 0; ni < 8; ni++) {
                int col = ni * 8 + 2 * t;
                float2 bv = *(const float2*)(bias + n0 + col);
                int i = col >> 1;
                float inv = powf(10000.f, -(float)(2 * i) / 64.f);
#pragma unroll
                for (int mi = 0; mi < 2; mi++) {
#pragma unroll
                    for (int hf = 0; hf < 2; hf++) {
                        int row = m0 + wm * 32 + mi * 16 + g + hf * 8;
                        float xe = acc[mi][ni][hf * 2 + 0] + bv.x;
                        float xo = acc[mi][ni][hf * 2 + 1] + bv.y;
                        float ang = (float)pos[row] * inv;
                        float sn, cs;
                        sincosf(ang, &sn, &cs);
                        float* dst = ks + (size_t)row * KD2 + 128 + 2 * i;
                        dst[0] = to_tf32(xe * cs - xo * sn);
                        dst[1] = to_tf32(xe * sn + xo * cs);
                    }
                }
            }
        }
    }
}

// ---------------- absorbed q GEMM: qs[b,h,s,192] ----------------
// cols per head: 0-127 q_eff, 128-159 q_nope tail, 160-191 rope(q_rope)
__global__ __launch_bounds__(256, 2)
void gemm_qnew_kernel(const float* __restrict__ A,
                      const float* __restrict__ B,
                      const float* __restrict__ bias,
                      const int* __restrict__ pos,
                      float* __restrict__ qs)
{
    GEMM_PREAMBLE
    int m0 = blockIdx.y * GBM;
    int n0 = blockIdx.x * GBN;
    GEMM_MAINLOOP(A, 128, B, QN2, 128, m0, n0)

#pragma unroll
    for (int ni = 0; ni < 8; ni++) {
        int col = n0 + wn * 64 + ni * 8 + 2 * t;
        float2 bv = *(const float2*)(bias + col);
        int h = col / KD2;
        int j = col - h * KD2;
#pragma unroll
        for (int mi = 0; mi < 2; mi++) {
#pragma unroll
            for (int hf = 0; hf < 2; hf++) {
                int row = m0 + wm * 32 + mi * 16 + g + hf * 8;
                float c0 = acc[mi][ni][hf * 2 + 0] + bv.x;
                float c1 = acc[mi][ni][hf * 2 + 1] + bv.y;
                float o0, o1;
                if (j < 160) {
                    o0 = c0; o1 = c1;
                } else {
                    int i = (j - 160) >> 1;
                    float ang = (float)pos[row] * powf(10000.f, -(float)(2 * i) / 32.f);
                    float sn, cs;
                    sincosf(ang, &sn, &cs);
                    o0 = c0 * cs - c1 * sn;
                    o1 = c0 * sn + c1 * cs;
                }
                int b = row >> 11, s = row & 2047;
                float* dst = qs + (((size_t)(b * 8 + h) * 2048 + s) * KD2 + j);
                dst[0] = to_tf32(o0 * SM_SCALE);
                dst[1] = to_tf32(o1 * SM_SCALE);
            }
        }
    }
}

// ---------------- absorbed flash attention ----------------
// Q [128 q x 192], K [64 keys x 192] head-shared, V = K cols 0-127 (dup buffer).
#define QS_STRIDE 196
#define KS_STRIDE 196
#define VS_STRIDE 136
#define PS_STRIDE 68
#define QS_OFF  0
#define KS_OFF  (QS_OFF + 128 * QS_STRIDE)    // 25088
#define VS_OFF  (KS_OFF + 64 * KS_STRIDE)     // 37632
#define PS_OFF  (VS_OFF + 64 * VS_STRIDE)     // 46336
#define STM_OFF (PS_OFF + 128 * PS_STRIDE)    // 55040
#define STS_OFF (STM_OFF + 256)               // 55296
#define FLASH_SMEM_FLOATS (STS_OFF + 256)     // 55552
#define FLASH_SMEM_BYTES  (FLASH_SMEM_FLOATS * 4)  // 222208
#define NKT (S_LEN / 64)

__global__ __launch_bounds__(512, 1)
void flash_mma_kernel(const float* __restrict__ qs, const float* __restrict__ ks,
                      float* __restrict__ attn)
{
    extern __shared__ float sm[];
    float* Qs  = sm + QS_OFF;
    float* Ks  = sm + KS_OFF;
    float* Vs  = sm + VS_OFF;
    float* Ps  = sm + PS_OFF;
    float* StM = sm + STM_OFF;
    float* StS = sm + STS_OFF;

    int b = blockIdx.z, h = blockIdx.y, qt = blockIdx.x;
    int tid  = threadIdx.x;
    int wid  = tid >> 5;
    int lane = tid & 31;
    int mw = wid >> 1;
    int nw = wid & 1;
    int g  = lane >> 2;
    int t  = lane & 3;

    size_t bh = (size_t)(b * NH + h) * S_LEN;
    const float* Kbase = ks + (size_t)b * S_LEN * KD2;

    auto load_k_tile = [&](int kt) {
        const float* Kg = Kbase + (size_t)kt * 64 * KD2;
#pragma unroll
        for (int p = 0; p < 6; p++) {           // 64*48 = 3072 float4
            int idx = tid + p * 512;
            int r = idx / 48, c = (idx % 48) * 4;
            cp_async16(&Ks[r * KS_STRIDE + c], Kg + r * KD2 + c);
        }
        CP_COMMIT();
    };
    auto load_v_tile = [&](int kt) {
        const float* Kg = Kbase + (size_t)kt * 64 * KD2;
#pragma unroll
        for (int p = 0; p < 4; p++) {           // 64*32 = 2048 float4 (cols 0-127)
            int idx = tid + p * 512;
            int r = idx >> 5, c = (idx & 31) * 4;
            cp_async16(&Vs[r * VS_STRIDE + c], Kg + r * KD2 + c);
        }
        CP_COMMIT();
    };

    load_k_tile(0);
    {
        const float4* Qg = (const float4*)(qs + (bh + (size_t)qt * 128) * KD2);
#pragma unroll
        for (int p = 0; p < 12; p++) {          // 128*48 = 6144 float4
            int idx = tid + p * 512;
            int r = idx / 48, c4 = idx % 48;
            *(float4*)&Qs[r * QS_STRIDE + c4 * 4] = Qg[r * 48 + c4];
        }
    }

    int qrow = mw * 16;
    float m0 = -1e30f, m1 = -1e30f, l0 = 0.f, l1 = 0.f;
    float o[8][4];
#pragma unroll
    for (int dt = 0; dt < 8; dt++)
#pragma unroll
        for (int j = 0; j < 4; j++) o[dt][j] = 0.f;

    for (int kt = 0; kt < NKT; kt++) {
        CP_WAIT0();
        __syncthreads();

        load_v_tile(kt);

        float c[4][4];
#pragma unroll
        for (int nt = 0; nt < 4; nt++)
#pragma unroll
            for (int j = 0; j < 4; j++) c[nt][j] = 0.f;

#pragma unroll
        for (int k8 = 0; k8 < 24; k8++) {
            int kc = k8 * 8;
            uint32_t a0 = __float_as_uint(Qs[(qrow + g) * QS_STRIDE + kc + t]);
            uint32_t a1 = __float_as_uint(Qs[(qrow + g + 8) * QS_STRIDE + kc + t]);
            uint32_t a2 = __float_as_uint(Qs[(qrow + g) * QS_STRIDE + kc + t + 4]);
            uint32_t a3 = __float_as_uint(Qs[(qrow + g + 8) * QS_STRIDE + kc + t + 4]);
#pragma unroll
            for (int nt = 0; nt < 4; nt++) {
                int ncol = nw * 32 + nt * 8 + g;
                uint32_t b0 = __float_as_uint(Ks[ncol * KS_STRIDE + kc + t]);
                uint32_t b1 = __float_as_uint(Ks[ncol * KS_STRIDE + kc + t + 4]);
                mma_tf32(c[nt], a0, a1, a2, a3, b0, b1);
            }
        }

        float pm0 = -1e30f, pm1 = -1e30f;
#pragma unroll
        for (int nt = 0; nt < 4; nt++) {
            pm0 = fmaxf(pm0, fmaxf(c[nt][0], c[nt][1]));
            pm1 = fmaxf(pm1, fmaxf(c[nt][2], c[nt][3]));
        }
        pm0 = fmaxf(pm0, __shfl_xor_sync(0xffffffffu, pm0, 1));
        pm0 = fmaxf(pm0, __shfl_xor_sync(0xffffffffu, pm0, 2));
        pm1 = fmaxf(pm1, __shfl_xor_sync(0xffffffffu, pm1, 1));
        pm1 = fmaxf(pm1, __shfl_xor_sync(0xffffffffu, pm1, 2));

        float ex[4][4];
        float ps0 = 0.f, ps1 = 0.f;
#pragma unroll
        for (int nt = 0; nt < 4; nt++) {
            ex[nt][0] = __expf(c[nt][0] - pm0);
            ex[nt][1] = __expf(c[nt][1] - pm0);
            ex[nt][2] = __expf(c[nt][2] - pm1);
            ex[nt][3] = __expf(c[nt][3] - pm1);
            ps0 += ex[nt][0] + ex[nt][1];
            ps1 += ex[nt][2] + ex[nt][3];
        }
        ps0 += __shfl_xor_sync(0xffffffffu, ps0, 1);
        ps0 += __shfl_xor_sync(0xffffffffu, ps0, 2);
        ps1 += __shfl_xor_sync(0xffffffffu, ps1, 1);
        ps1 += __shfl_xor_sync(0xffffffffu, ps1, 2);

        if (t == 0) {
            StM[nw * 128 + qrow + g]     = pm0;
            StM[nw * 128 + qrow + g + 8] = pm1;
            StS[nw * 128 + qrow + g]     = ps0;
            StS[nw * 128 + qrow + g + 8] = ps1;
        }
        __syncthreads();

        if (kt + 1 < NKT) load_k_tile(kt + 1);

        int ow = 1 - nw;
        float pmO0 = StM[ow * 128 + qrow + g];
        float pmO1 = StM[ow * 128 + qrow + g + 8];
        float psO0 = StS[ow * 128 + qrow + g];
        float psO1 = StS[ow * 128 + qrow + g + 8];

        float mn0 = fmaxf(pm0, pmO0);
        float mn1 = fmaxf(pm1, pmO1);
        float rs0 = ps0 * __expf(pm0 - mn0) + psO0 * __expf(pmO0 - mn0);
        float rs1 = ps1 * __expf(pm1 - mn1) + psO1 * __expf(pmO1 - mn1);

        float mnew0 = fmaxf(m0, mn0);
        float mnew1 = fmaxf(m1, mn1);
        float corr0 = __expf(m0 - mnew0);
        float corr1 = __expf(m1 - mnew1);
        l0 = l0 * corr0 + rs0 * __expf(mn0 - mnew0);
        l1 = l1 * corr1 + rs1 * __expf(mn1 - mnew1);
        m0 = mnew0;
        m1 = mnew1;

#pragma unroll
        for (int dt = 0; dt < 8; dt++) {
            o[dt][0] *= corr0;
            o[dt][1] *= corr0;
            o[dt][2] *= corr1;
            o[dt][3] *= corr1;
        }

        float f0 = __expf(pm0 - mnew0);
        float f1 = __expf(pm1 - mnew1);
#pragma unroll
        for (int nt = 0; nt < 4; nt++) {
            int col = nw * 32 + nt * 8 + 2 * t;
            *(float2*)&Ps[(qrow + g) * PS_STRIDE + col] =
                make_float2(to_tf32(ex[nt][0] * f0), to_tf32(ex[nt][1] * f0));
            *(float2*)&Ps[(qrow + g + 8) * PS_STRIDE + col] =
                make_float2(to_tf32(ex[nt][2] * f1), to_tf32(ex[nt][3] * f1));
        }

        if (kt + 1 < NKT) { CP_WAIT1(); } else { CP_WAIT0(); }
        __syncthreads();

#pragma unroll
        for (int k8 = 0; k8 < 8; k8++) {
            int kc = k8 * 8;
            uint32_t a0 = __float_as_uint(Ps[(qrow + g) * PS_STRIDE + kc + t]);
            uint32_t a1 = __float_as_uint(Ps[(qrow + g + 8) * PS_STRIDE + kc + t]);
            uint32_t a2 = __float_as_uint(Ps[(qrow + g) * PS_STRIDE + kc + t + 4]);
            uint32_t a3 = __float_as_uint(Ps[(qrow + g + 8) * PS_STRIDE + kc + t + 4]);
#pragma unroll
            for (int dt = 0; dt < 8; dt++) {
                int dv = nw * 64 + dt * 8 + g;
                uint32_t b0 = __float_as_uint(Vs[(kc + t) * VS_STRIDE + dv]);
                uint32_t b1 = __float_as_uint(Vs[(kc + t + 4) * VS_STRIDE + dv]);
                mma_tf32(o[dt], a0, a1, a2, a3, b0, b1);
            }
        }
    }

    // epilogue: attn[row, h*128 + dv] = Pckv / l (tf32)
    float inv0 = 1.f / l0;
    float inv1 = 1.f / l1;
    int row0 = b * S_LEN + qt * 128 + qrow + g;
    int row1 = row0 + 8;
#pragma unroll
    for (int dt = 0; dt < 8; dt++) {
        int col = h * 128 + nw * 64 + dt * 8 + 2 * t;
        float2 v0 = make_float2(to_tf32(o[dt][0] * inv0), to_tf32(o[dt][1] * inv0));
        float2 v1 = make_float2(to_tf32(o[dt][2] * inv1), to_tf32(o[dt][3] * inv1));
        *(float2*)(attn + (size_t)row0 * 1024 + col) = v0;
        *(float2*)(attn + (size_t)row1 * 1024 + col) = v1;
    }
}

// ---------------- host launcher ----------------
extern "C" void kernel_launch(void* const* d_in, const int* in_sizes, int n_in,
                              void* d_out, int out_size)
{
    const float* x         = (const float*)d_in[0];
    const int*   pos       = (const int*)  d_in[1];
    const float* w_dq_w    = (const float*)d_in[2];
    const float* w_dq_b    = (const float*)d_in[3];
    const float* q_norm_w  = (const float*)d_in[4];
    const float* w_uq_qr_w = (const float*)d_in[5];
    const float* w_uq_qr_b = (const float*)d_in[6];
    const float* w_dkv_kr_w= (const float*)d_in[7];
    const float* w_dkv_kr_b= (const float*)d_in[8];
    const float* kv_norm_w = (const float*)d_in[9];
    const float* w_uk_uv_w = (const float*)d_in[10];
    const float* w_uk_uv_b = (const float*)d_in[11];
    const float* w_o_w     = (const float*)d_in[12];
    const float* w_o_b     = (const float*)d_in[13];
    float* out = (float*)d_out;

    float *cq, *ksb, *qsb, *attn;
    float *x32, *w13, *b13, *w2, *w4, *w5, *wqn, *bqn, *weff, *beff;
    cudaGetSymbolAddress((void**)&cq,   g_cq);
    cudaGetSymbolAddress((void**)&ksb,  g_ks);
    cudaGetSymbolAddress((void**)&qsb,  g_qs);
    cudaGetSymbolAddress((void**)&attn, g_attn);
    cudaGetSymbolAddress((void**)&x32,  g_x32);
    cudaGetSymbolAddress((void**)&w13,  g_w13);
    cudaGetSymbolAddress((void**)&b13,  g_b13);
    cudaGetSymbolAddress((void**)&w2,   g_w2);
    cudaGetSymbolAddress((void**)&w4,   g_w4);
    cudaGetSymbolAddress((void**)&w5,   g_w5);
    cudaGetSymbolAddress((void**)&wqn,  g_wqn);
    cudaGetSymbolAddress((void**)&bqn,  g_bqn);
    cudaGetSymbolAddress((void**)&weff, g_weff);
    cudaGetSymbolAddress((void**)&beff, g_beff);

    cudaFuncSetAttribute(flash_mma_kernel, cudaFuncAttributeMaxDynamicSharedMemorySize,
                         FLASH_SMEM_BYTES);
    cudaFuncSetAttribute(gemm_tf32_kernel, cudaFuncAttributeMaxDynamicSharedMemorySize,
                         GEMM_SMEM_BYTES);
    cudaFuncSetAttribute(gemm_cqkv_kernel, cudaFuncAttributeMaxDynamicSharedMemorySize,
                         GEMM_SMEM_BYTES);
    cudaFuncSetAttribute(gemm_qnew_kernel, cudaFuncAttributeMaxDynamicSharedMemorySize,
                         GEMM_SMEM_BYTES);
    cudaFuncSetAttribute(gemm_weff_kernel, cudaFuncAttributeMaxDynamicSharedMemorySize,
                         GEMM_SMEM_BYTES);

    round_all_kernel<<<(RA_TOTAL + 255) / 256, 256>>>(
        x, x32, w_uq_qr_w, w2, w_uk_uv_w, w4, w_o_w, w5,
        w_dq_w, w_dkv_kr_w, w13, w_dq_b, w_dkv_kr_b, b13);

    // precomputes (absorbed weights)
    precompute_wq_kernel<<<(128 * QN2 + 255) / 256, 256>>>(w2, w4, w_uq_qr_b, wqn, bqn);
    gemm_weff_kernel<<<dim3(8, 1, 8), 256, GEMM_SMEM_BYTES>>>(w4, w5, weff);
    precompute_beff_kernel<<<4, 256>>>(w_uk_uv_b, w_o_w, w_o_b, beff);

    dim3 blk(256);

    gemm_cqkv_kernel<<<dim3(3, NROWS / GBM), blk, GEMM_SMEM_BYTES>>>(
        x32, w13, b13, q_norm_w, kv_norm_w, pos, cq, ksb);

    gemm_qnew_kernel<<<dim3(QN2 / GBN, NROWS / GBM), blk, GEMM_SMEM_BYTES>>>(
        cq, wqn, bqn, pos, qsb);

    flash_mma_kernel<<<dim3(S_LEN / 128, NH, BATCH), 512, FLASH_SMEM_BYTES>>>(qsb, ksb, attn);

    gemm_tf32_kernel<<<dim3(1024 / GBN, NROWS / GBM), blk, GEMM_SMEM_BYTES>>>(
        attn, 1024, weff, beff, out, NROWS, 1024, 1024);
}

// round 12
// speedup vs baseline: 1.1270x; 1.1270x over previous
#include <cuda_runtime.h>
#include <math.h>
#include <stdint.h>

// ---------------- problem constants ----------------
#define BATCH   2
#define S_LEN   2048
#define NROWS   (BATCH * S_LEN)     // 4096
#define DIM_    1024
#define NH      8
#define SM_SCALE 0.08838834764831845f   // 1/sqrt(128)
#define CQKV_N  384                      // 128 (cq) + 192 (ckv_kr) + 64 pad
#define KD2     192                      // absorbed K dim: 128 ckv + 64 rope
#define QN2     1536                     // 8 heads * 192

// ---------------- scratch ----------------
__device__ float g_cq   [(size_t)NROWS * 128];
__device__ float g_ks   [(size_t)NROWS * KD2];               // [b,s,192] head-shared
__device__ float g_qs   [(size_t)BATCH * NH * S_LEN * KD2];  // [b,h,s,192]
__device__ float g_attn [(size_t)NROWS * 1024];              // P@ckv concat heads
__device__ float g_x32  [(size_t)NROWS * DIM_];
__device__ float g_w13  [(size_t)DIM_ * CQKV_N];
__device__ float g_b13  [CQKV_N];
__device__ float g_w2   [(size_t)128 * 1024];
__device__ float g_w4   [(size_t)128 * 2560];
__device__ float g_w5   [(size_t)2048 * DIM_];
__device__ float g_wqn  [(size_t)128 * QN2];                 // absorbed q weights
__device__ float g_bqn  [QN2];
__device__ float g_weff [(size_t)1024 * 1024];               // W_uv @ W_o
__device__ float g_beff [1024];

// ---------------- helpers ----------------
__device__ __forceinline__ float to_tf32(float x) {
    uint32_t u;
    asm("cvt.rna.tf32.f32 %0, %1;" : "=r"(u) : "f"(x));
    return __uint_as_float(u);
}

__device__ __forceinline__ void mma_tf32(float* c, uint32_t a0, uint32_t a1,
                                         uint32_t a2, uint32_t a3,
                                         uint32_t b0, uint32_t b1) {
    asm volatile(
        "mma.sync.aligned.m16n8k8.row.col.f32.tf32.tf32.f32 "
        "{%0,%1,%2,%3}, {%4,%5,%6,%7}, {%8,%9}, {%0,%1,%2,%3};"
        : "+f"(c[0]), "+f"(c[1]), "+f"(c[2]), "+f"(c[3])
        : "r"(a0), "r"(a1), "r"(a2), "r"(a3), "r"(b0), "r"(b1));
}

__device__ __forceinline__ void cp_async16(void* smem_ptr, const void* gptr) {
    uint32_t s = (uint32_t)__cvta_generic_to_shared(smem_ptr);
    asm volatile("cp.async.cg.shared.global [%0], [%1], 16;" :: "r"(s), "l"(gptr));
}
#define CP_COMMIT() asm volatile("cp.async.commit_group;")
#define CP_WAIT0()  asm volatile("cp.async.wait_group 0;")
#define CP_WAIT1()  asm volatile("cp.async.wait_group 1;")

// ---------------- tf32 rounding / w13 packing ----------------
#define RA_X   1048576
#define RA_W2  (RA_X  + 32768)
#define RA_W4  (RA_W2 + 81920)
#define RA_W5  (RA_W4 + 524288)
#define RA_W13 (RA_W5 + 98304)
#define RA_B13 (RA_W13 + 96)
#define RA_TOTAL RA_B13

__global__ __launch_bounds__(256)
void round_all_kernel(const float* __restrict__ x,    float* __restrict__ ox,
                      const float* __restrict__ w2i,  float* __restrict__ w2o,
                      const float* __restrict__ w4i,  float* __restrict__ w4o,
                      const float* __restrict__ w5i,  float* __restrict__ w5o,
                      const float* __restrict__ w1i,  const float* __restrict__ w3i,
                      float* __restrict__ w13o,
                      const float* __restrict__ b1i,  const float* __restrict__ b3i,
                      float* __restrict__ b13o)
{
    int i = blockIdx.x * 256 + threadIdx.x;
    if (i >= RA_TOTAL) return;
    float4 v;
    float4* dst;
    if (i < RA_X)       { v = ((const float4*)x)[i];             dst = (float4*)ox  + i; }
    else if (i < RA_W2) { int o = i - RA_X;  v = ((const float4*)w2i)[o]; dst = (float4*)w2o + o; }
    else if (i < RA_W4) { int o = i - RA_W2; v = ((const float4*)w4i)[o]; dst = (float4*)w4o + o; }
    else if (i < RA_W5) { int o = i - RA_W4; v = ((const float4*)w5i)[o]; dst = (float4*)w5o + o; }
    else if (i < RA_W13) {
        int o = i - RA_W5;
        int k = o / 96, c4 = (o % 96) * 4;
        if (c4 < 128)      v = *(const float4*)(w1i + (size_t)k * 128 + c4);
        else if (c4 < 320) v = *(const float4*)(w3i + (size_t)k * 192 + (c4 - 128));
        else               v = make_float4(0.f, 0.f, 0.f, 0.f);
        dst = (float4*)w13o + o;
    } else {
        int o = i - RA_W13;
        int c4 = o * 4;
        if (c4 < 128)      v = *(const float4*)(b1i + c4);
        else if (c4 < 320) v = *(const float4*)(b3i + (c4 - 128));
        else               v = make_float4(0.f, 0.f, 0.f, 0.f);
        *(float4*)(b13o + c4) = v;
        return;
    }
    v.x = to_tf32(v.x); v.y = to_tf32(v.y);
    v.z = to_tf32(v.z); v.w = to_tf32(v.w);
    *dst = v;
}

// ---------------- absorbed q-weight precompute ----------------
__global__ __launch_bounds__(256)
void precompute_wq_kernel(const float* __restrict__ w2r, const float* __restrict__ w4r,
                          const float* __restrict__ b2,  float* __restrict__ wqn,
                          float* __restrict__ bqn)
{
    int idx = blockIdx.x * 256 + threadIdx.x;
    if (idx >= 128 * QN2) return;
    int r = idx / QN2;
    int c = idx % QN2;
    int h = c / KD2;
    int j = c - h * KD2;
    float val, bv = 0.f;
    if (j < 128) {
        float s = 0.f, bs = 0.f;
        const float* w2p = w2r + (size_t)r * 1024 + h * 96;
        const float* w4p = w4r + (size_t)j * 2560 + h * 64;
        const float* b2p = b2 + h * 96;
#pragma unroll 8
        for (int d = 0; d < 64; d++) {
            s  += w2p[d] * w4p[d];
            bs += b2p[d] * w4p[d];
        }
        val = to_tf32(s);
        bv = bs;
    } else if (j < 160) {
        val = w2r[(size_t)r * 1024 + h * 96 + 64 + (j - 128)];
        bv  = b2[h * 96 + 64 + (j - 128)];
    } else {
        val = w2r[(size_t)r * 1024 + 768 + h * 32 + (j - 160)];
        bv  = b2[768 + h * 32 + (j - 160)];
    }
    wqn[(size_t)r * QN2 + c] = val;
    if (r == 0) bqn[c] = bv;
}

// ---------------- b_eff = b_o + b_v @ W_o (parallel reduction) ----------------
// 64 blocks x 256 threads; block owns 16 j-cols; threads = 16 j x 16 r-chunks(128).
__global__ __launch_bounds__(256)
void precompute_beff_kernel(const float* __restrict__ b45, const float* __restrict__ w_o,
                            const float* __restrict__ b_o, float* __restrict__ beff)
{
    __shared__ float red[256];
    int jb = blockIdx.x * 16;
    int tj = threadIdx.x & 15;
    int tr = threadIdx.x >> 4;
    int j = jb + tj;
    float s = 0.f;
    int r0 = tr * 128;
#pragma unroll 4
    for (int r = r0; r < r0 + 128; r++)
        s += b45[512 + r] * w_o[(size_t)r * 1024 + j];
    red[threadIdx.x] = s;
    __syncthreads();
    if (threadIdx.x < 16) {
        float acc = b_o[jb + threadIdx.x];
#pragma unroll
        for (int k = 0; k < 16; k++) acc += red[k * 16 + threadIdx.x];
        beff[jb + threadIdx.x] = acc;
    }
}

// ================= TF32 GEMM core (CTA 128x128, BK=32, 256 thr) =================
#define GBM 128
#define GBN 128
#define GBK 32
#define AS_STRIDE 36
#define BS_STRIDE 136
#define ABUF (GBM * AS_STRIDE)
#define BBUF (GBK * BS_STRIDE)
#define GEMM_SMEM_FLOATS (2 * (ABUF + BBUF))
#define GEMM_SMEM_BYTES  (GEMM_SMEM_FLOATS * 4)

#define GEMM_MAINLOOP(A, lda, B, N, K, m0, n0)                                        \
    float acc[2][8][4];                                                               \
    _Pragma("unroll") for (int mi = 0; mi < 2; mi++)                                  \
    _Pragma("unroll") for (int ni = 0; ni < 8; ni++)                                  \
    _Pragma("unroll") for (int j = 0; j < 4; j++) acc[mi][ni][j] = 0.f;               \
    int nk = (K) / GBK;                                                               \
    auto load_tile = [&](int kt, int bufi) {                                          \
        float* As_ = sm + bufi * (ABUF + BBUF);                                       \
        float* Bs_ = As_ + ABUF;                                                      \
        int k0 = kt * GBK;                                                            \
        _Pragma("unroll") for (int p = 0; p < 4; p++) {                               \
            int idx = tid + p * 256;                                                  \
            int r = idx >> 3, c = (idx & 7) * 4;                                      \
            cp_async16(&As_[r * AS_STRIDE + c], (A) + (size_t)((m0) + r) * (lda) + k0 + c); \
        }                                                                             \
        _Pragma("unroll") for (int p = 0; p < 4; p++) {                               \
            int idx = tid + p * 256;                                                  \
            int r = idx >> 5, c = (idx & 31) * 4;                                     \
            cp_async16(&Bs_[r * BS_STRIDE + c], (B) + (size_t)(k0 + r) * (N) + (n0) + c); \
        }                                                                             \
        CP_COMMIT();                                                                  \
    };                                                                                \
    load_tile(0, 0);                                                                  \
    for (int kt = 0; kt < nk; kt++) {                                                 \
        int bufi = kt & 1;                                                            \
        if (kt + 1 < nk) { load_tile(kt + 1, bufi ^ 1); CP_WAIT1(); }                 \
        else            { CP_WAIT0(); }                                               \
        __syncthreads();                                                              \
        const float* As_ = sm + bufi * (ABUF + BBUF);                                 \
        const float* Bs_ = As_ + ABUF;                                                \
        _Pragma("unroll") for (int k8 = 0; k8 < 4; k8++) {                            \
            int kc = k8 * 8;                                                          \
            uint32_t a[2][4];                                                         \
            _Pragma("unroll") for (int mi = 0; mi < 2; mi++) {                        \
                int row = wm * 32 + mi * 16;                                          \
                a[mi][0] = __float_as_uint(As_[(row + g) * AS_STRIDE + kc + t]);      \
                a[mi][1] = __float_as_uint(As_[(row + g + 8) * AS_STRIDE + kc + t]);  \
                a[mi][2] = __float_as_uint(As_[(row + g) * AS_STRIDE + kc + t + 4]);  \
                a[mi][3] = __float_as_uint(As_[(row + g + 8) * AS_STRIDE + kc + t + 4]); \
            }                                                                         \
            _Pragma("unroll") for (int ni = 0; ni < 8; ni++) {                        \
                int col = wn * 64 + ni * 8 + g;                                       \
                uint32_t b0 = __float_as_uint(Bs_[(kc + t) * BS_STRIDE + col]);       \
                uint32_t b1 = __float_as_uint(Bs_[(kc + t + 4) * BS_STRIDE + col]);   \
                mma_tf32(acc[0][ni], a[0][0], a[0][1], a[0][2], a[0][3], b0, b1);     \
                mma_tf32(acc[1][ni], a[1][0], a[1][1], a[1][2], a[1][3], b0, b1);     \
            }                                                                         \
        }                                                                             \
        __syncthreads();                                                              \
    }

#define GEMM_PREAMBLE                  \
    extern __shared__ float sm[];      \
    int tid  = threadIdx.x;            \
    int wid  = tid >> 5;               \
    int lane = tid & 31;               \
    int wm = wid >> 1;                 \
    int wn = wid & 1;                  \
    int g  = lane >> 2;                \
    int t  = lane & 3;

// ---------------- plain GEMM + bias, fp32 out ----------------
__global__ __launch_bounds__(256, 2)
void gemm_tf32_kernel(const float* __restrict__ A, int lda,
                      const float* __restrict__ B,
                      const float* __restrict__ bias,
                      float* __restrict__ C,
                      int M, int N, int K)
{
    GEMM_PREAMBLE
    int m0 = blockIdx.y * GBM;
    int n0 = blockIdx.x * GBN;
    GEMM_MAINLOOP(A, lda, B, N, K, m0, n0)

#pragma unroll
    for (int ni = 0; ni < 8; ni++) {
        int col = n0 + wn * 64 + ni * 8 + 2 * t;
        float2 bv = *(const float2*)(bias + col);
#pragma unroll
        for (int mi = 0; mi < 2; mi++) {
            int r0 = m0 + wm * 32 + mi * 16 + g;
            float2 v0 = make_float2(acc[mi][ni][0] + bv.x, acc[mi][ni][1] + bv.y);
            float2 v1 = make_float2(acc[mi][ni][2] + bv.x, acc[mi][ni][3] + bv.y);
            *(float2*)(C + (size_t)r0 * N + col) = v0;
            *(float2*)(C + (size_t)(r0 + 8) * N + col) = v1;
        }
    }
}

// ---------------- W_eff batched GEMM: W_eff_h = W_uv_h @ W_o_h ----------------
__global__ __launch_bounds__(256, 2)
void gemm_weff_kernel(const float* __restrict__ w4r, const float* __restrict__ w5r,
                      float* __restrict__ weff)
{
    GEMM_PREAMBLE
    int h = blockIdx.z;
    int m0 = 0;
    int n0 = blockIdx.x * GBN;
    const float* A = w4r + 512 + h * 256;
    const float* B = w5r + (size_t)h * 256 * 1024;
    GEMM_MAINLOOP(A, 2560, B, 1024, 256, m0, n0)

#pragma unroll
    for (int ni = 0; ni < 8; ni++) {
        int col = n0 + wn * 64 + ni * 8 + 2 * t;
#pragma unroll
        for (int mi = 0; mi < 2; mi++) {
            int r0 = h * 128 + wm * 32 + mi * 16 + g;
            float2 v0 = make_float2(to_tf32(acc[mi][ni][0]), to_tf32(acc[mi][ni][1]));
            float2 v1 = make_float2(to_tf32(acc[mi][ni][2]), to_tf32(acc[mi][ni][3]));
            *(float2*)(weff + (size_t)r0 * 1024 + col) = v0;
            *(float2*)(weff + (size_t)(r0 + 8) * 1024 + col) = v1;
        }
    }
}

// ---------------- cqkv GEMM (A = pre-rounded x32) ----------------
#define STG_STRIDE 129
__global__ __launch_bounds__(256, 2)
void gemm_cqkv_kernel(const float* __restrict__ A,
                      const float* __restrict__ B,
                      const float* __restrict__ bias,
                      const float* __restrict__ wq_norm,
                      const float* __restrict__ wkv_norm,
                      const int* __restrict__ pos,
                      float* __restrict__ cq,
                      float* __restrict__ ks)
{
    GEMM_PREAMBLE
    int m0 = blockIdx.y * GBM;
    int tileN = blockIdx.x;            // 0,1,2
    int n0 = tileN * GBN;
    GEMM_MAINLOOP(A, DIM_, B, CQKV_N, DIM_, m0, n0)

    if (tileN < 2) {
        float* stage = sm;
        float* scl   = sm + 128 * STG_STRIDE;
#pragma unroll
        for (int ni = 0; ni < 8; ni++) {
            int col = wn * 64 + ni * 8 + 2 * t;
            float2 bv = *(const float2*)(bias + n0 + col);
#pragma unroll
            for (int mi = 0; mi < 2; mi++) {
#pragma unroll
                for (int hf = 0; hf < 2; hf++) {
                    int rowl = wm * 32 + mi * 16 + g + hf * 8;
                    stage[rowl * STG_STRIDE + col]     = acc[mi][ni][hf * 2 + 0] + bv.x;
                    stage[rowl * STG_STRIDE + col + 1] = acc[mi][ni][hf * 2 + 1] + bv.y;
                }
            }
        }
        __syncthreads();
        if (tid < 128) {
            const float* rp = stage + tid * STG_STRIDE;
            float ssq = 0.f;
#pragma unroll 16
            for (int c = 0; c < 128; c++) ssq += rp[c] * rp[c];
            scl[tid] = rsqrtf(ssq * (1.f / 128.f) + 1e-8f);
        }
        __syncthreads();
        const float* w = (tileN == 0) ? wq_norm : wkv_norm;
        for (int idx = tid; idx < 128 * 128; idx += 256) {
            int row = idx >> 7, col = idx & 127;
            float v = to_tf32(stage[row * STG_STRIDE + col] * w[col] * scl[row]);
            if (tileN == 0) cq[(size_t)(m0 + row) * 128 + col] = v;
            else            ks[(size_t)(m0 + row) * KD2 + col] = v;
        }
    } else {
        if (wn == 0) {
#pragma unroll
            for (int ni = 0; ni < 8; ni++) {
                int col = ni * 8 + 2 * t;
                float2 bv = *(const float2*)(bias + n0 + col);
                int i = col >> 1;
                float inv = powf(10000.f, -(float)(2 * i) / 64.f);
#pragma unroll
                for (int mi = 0; mi < 2; mi++) {
#pragma unroll
                    for (int hf = 0; hf < 2; hf++) {
                        int row = m0 + wm * 32 + mi * 16 + g + hf * 8;
                        float xe = acc[mi][ni][hf * 2 + 0] + bv.x;
                        float xo = acc[mi][ni][hf * 2 + 1] + bv.y;
                        float ang = (float)pos[row] * inv;
                        float sn, cs;
                        sincosf(ang, &sn, &cs);
                        float* dst = ks + (size_t)row * KD2 + 128 + 2 * i;
                        dst[0] = to_tf32(xe * cs - xo * sn);
                        dst[1] = to_tf32(xe * sn + xo * cs);
                    }
                }
            }
        }
    }
}

// ---------------- absorbed q GEMM: qs[b,h,s,192] ----------------
__global__ __launch_bounds__(256, 2)
void gemm_qnew_kernel(const float* __restrict__ A,
                      const float* __restrict__ B,
                      const float* __restrict__ bias,
                      const int* __restrict__ pos,
                      float* __restrict__ qs)
{
    GEMM_PREAMBLE
    int m0 = blockIdx.y * GBM;
    int n0 = blockIdx.x * GBN;
    GEMM_MAINLOOP(A, 128, B, QN2, 128, m0, n0)

#pragma unroll
    for (int ni = 0; ni < 8; ni++) {
        int col = n0 + wn * 64 + ni * 8 + 2 * t;
        float2 bv = *(const float2*)(bias + col);
        int h = col / KD2;
        int j = col - h * KD2;
#pragma unroll
        for (int mi = 0; mi < 2; mi++) {
#pragma unroll
            for (int hf = 0; hf < 2; hf++) {
                int row = m0 + wm * 32 + mi * 16 + g + hf * 8;
                float c0 = acc[mi][ni][hf * 2 + 0] + bv.x;
                float c1 = acc[mi][ni][hf * 2 + 1] + bv.y;
                float o0, o1;
                if (j < 160) {
                    o0 = c0; o1 = c1;
                } else {
                    int i = (j - 160) >> 1;
                    float ang = (float)pos[row] * powf(10000.f, -(float)(2 * i) / 32.f);
                    float sn, cs;
                    sincosf(ang, &sn, &cs);
                    o0 = c0 * cs - c1 * sn;
                    o1 = c0 * sn + c1 * cs;
                }
                int b = row >> 11, s = row & 2047;
                float* dst = qs + (((size_t)(b * 8 + h) * 2048 + s) * KD2 + j);
                dst[0] = to_tf32(o0 * SM_SCALE);
                dst[1] = to_tf32(o1 * SM_SCALE);
            }
        }
    }
}

// ---------------- absorbed flash attention ----------------
#define QS_STRIDE 196
#define KS_STRIDE 196
#define VS_STRIDE 136
#define PS_STRIDE 68
#define QS_OFF  0
#define KS_OFF  (QS_OFF + 128 * QS_STRIDE)
#define VS_OFF  (KS_OFF + 64 * KS_STRIDE)
#define PS_OFF  (VS_OFF + 64 * VS_STRIDE)
#define STM_OFF (PS_OFF + 128 * PS_STRIDE)
#define STS_OFF (STM_OFF + 256)
#define FLASH_SMEM_FLOATS (STS_OFF + 256)
#define FLASH_SMEM_BYTES  (FLASH_SMEM_FLOATS * 4)
#define NKT (S_LEN / 64)

__global__ __launch_bounds__(512, 1)
void flash_mma_kernel(const float* __restrict__ qs, const float* __restrict__ ks,
                      float* __restrict__ attn)
{
    extern __shared__ float sm[];
    float* Qs  = sm + QS_OFF;
    float* Ks  = sm + KS_OFF;
    float* Vs  = sm + VS_OFF;
    float* Ps  = sm + PS_OFF;
    float* StM = sm + STM_OFF;
    float* StS = sm + STS_OFF;

    int b = blockIdx.z, h = blockIdx.y, qt = blockIdx.x;
    int tid  = threadIdx.x;
    int wid  = tid >> 5;
    int lane = tid & 31;
    int mw = wid >> 1;
    int nw = wid & 1;
    int g  = lane >> 2;
    int t  = lane & 3;

    size_t bh = (size_t)(b * NH + h) * S_LEN;
    const float* Kbase = ks + (size_t)b * S_LEN * KD2;

    auto load_k_tile = [&](int kt) {
        const float* Kg = Kbase + (size_t)kt * 64 * KD2;
#pragma unroll
        for (int p = 0; p < 6; p++) {
            int idx = tid + p * 512;
            int r = idx / 48, c = (idx % 48) * 4;
            cp_async16(&Ks[r * KS_STRIDE + c], Kg + r * KD2 + c);
        }
        CP_COMMIT();
    };
    auto load_v_tile = [&](int kt) {
        const float* Kg = Kbase + (size_t)kt * 64 * KD2;
#pragma unroll
        for (int p = 0; p < 4; p++) {
            int idx = tid + p * 512;
            int r = idx >> 5, c = (idx & 31) * 4;
            cp_async16(&Vs[r * VS_STRIDE + c], Kg + r * KD2 + c);
        }
        CP_COMMIT();
    };

    load_k_tile(0);
    {
        const float4* Qg = (const float4*)(qs + (bh + (size_t)qt * 128) * KD2);
#pragma unroll
        for (int p = 0; p < 12; p++) {
            int idx = tid + p * 512;
            int r = idx / 48, c4 = idx % 48;
            *(float4*)&Qs[r * QS_STRIDE + c4 * 4] = Qg[r * 48 + c4];
        }
    }

    int qrow = mw * 16;
    float m0 = -1e30f, m1 = -1e30f, l0 = 0.f, l1 = 0.f;
    float o[8][4];
#pragma unroll
    for (int dt = 0; dt < 8; dt++)
#pragma unroll
        for (int j = 0; j < 4; j++) o[dt][j] = 0.f;

    for (int kt = 0; kt < NKT; kt++) {
        CP_WAIT0();
        __syncthreads();

        load_v_tile(kt);

        float c[4][4];
#pragma unroll
        for (int nt = 0; nt < 4; nt++)
#pragma unroll
            for (int j = 0; j < 4; j++) c[nt][j] = 0.f;

#pragma unroll
        for (int k8 = 0; k8 < 24; k8++) {
            int kc = k8 * 8;
            uint32_t a0 = __float_as_uint(Qs[(qrow + g) * QS_STRIDE + kc + t]);
            uint32_t a1 = __float_as_uint(Qs[(qrow + g + 8) * QS_STRIDE + kc + t]);
            uint32_t a2 = __float_as_uint(Qs[(qrow + g) * QS_STRIDE + kc + t + 4]);
            uint32_t a3 = __float_as_uint(Qs[(qrow + g + 8) * QS_STRIDE + kc + t + 4]);
#pragma unroll
            for (int nt = 0; nt < 4; nt++) {
                int ncol = nw * 32 + nt * 8 + g;
                uint32_t b0 = __float_as_uint(Ks[ncol * KS_STRIDE + kc + t]);
                uint32_t b1 = __float_as_uint(Ks[ncol * KS_STRIDE + kc + t + 4]);
                mma_tf32(c[nt], a0, a1, a2, a3, b0, b1);
            }
        }

        float pm0 = -1e30f, pm1 = -1e30f;
#pragma unroll
        for (int nt = 0; nt < 4; nt++) {
            pm0 = fmaxf(pm0, fmaxf(c[nt][0], c[nt][1]));
            pm1 = fmaxf(pm1, fmaxf(c[nt][2], c[nt][3]));
        }
        pm0 = fmaxf(pm0, __shfl_xor_sync(0xffffffffu, pm0, 1));
        pm0 = fmaxf(pm0, __shfl_xor_sync(0xffffffffu, pm0, 2));
        pm1 = fmaxf(pm1, __shfl_xor_sync(0xffffffffu, pm1, 1));
        pm1 = fmaxf(pm1, __shfl_xor_sync(0xffffffffu, pm1, 2));

        float ex[4][4];
        float ps0 = 0.f, ps1 = 0.f;
#pragma unroll
        for (int nt = 0; nt < 4; nt++) {
            ex[nt][0] = __expf(c[nt][0] - pm0);
            ex[nt][1] = __expf(c[nt][1] - pm0);
            ex[nt][2] = __expf(c[nt][2] - pm1);
            ex[nt][3] = __expf(c[nt][3] - pm1);
            ps0 += ex[nt][0] + ex[nt][1];
            ps1 += ex[nt][2] + ex[nt][3];
        }
        ps0 += __shfl_xor_sync(0xffffffffu, ps0, 1);
        ps0 += __shfl_xor_sync(0xffffffffu, ps0, 2);
        ps1 += __shfl_xor_sync(0xffffffffu, ps1, 1);
        ps1 += __shfl_xor_sync(0xffffffffu, ps1, 2);

        if (t == 0) {
            StM[nw * 128 + qrow + g]     = pm0;
            StM[nw * 128 + qrow + g + 8] = pm1;
            StS[nw * 128 + qrow + g]     = ps0;
            StS[nw * 128 + qrow + g + 8] = ps1;
        }
        __syncthreads();

        if (kt + 1 < NKT) load_k_tile(kt + 1);

        int ow = 1 - nw;
        float pmO0 = StM[ow * 128 + qrow + g];
        float pmO1 = StM[ow * 128 + qrow + g + 8];
        float psO0 = StS[ow * 128 + qrow + g];
        float psO1 = StS[ow * 128 + qrow + g + 8];

        float mn0 = fmaxf(pm0, pmO0);
        float mn1 = fmaxf(pm1, pmO1);
        float rs0 = ps0 * __expf(pm0 - mn0) + psO0 * __expf(pmO0 - mn0);
        float rs1 = ps1 * __expf(pm1 - mn1) + psO1 * __expf(pmO1 - mn1);

        float mnew0 = fmaxf(m0, mn0);
        float mnew1 = fmaxf(m1, mn1);
        float corr0 = __expf(m0 - mnew0);
        float corr1 = __expf(m1 - mnew1);
        l0 = l0 * corr0 + rs0 * __expf(mn0 - mnew0);
        l1 = l1 * corr1 + rs1 * __expf(mn1 - mnew1);
        m0 = mnew0;
        m1 = mnew1;

#pragma unroll
        for (int dt = 0; dt < 8; dt++) {
            o[dt][0] *= corr0;
            o[dt][1] *= corr0;
            o[dt][2] *= corr1;
            o[dt][3] *= corr1;
        }

        float f0 = __expf(pm0 - mnew0);
        float f1 = __expf(pm1 - mnew1);
#pragma unroll
        for (int nt = 0; nt < 4; nt++) {
            int col = nw * 32 + nt * 8 + 2 * t;
            *(float2*)&Ps[(qrow + g) * PS_STRIDE + col] =
                make_float2(to_tf32(ex[nt][0] * f0), to_tf32(ex[nt][1] * f0));
            *(float2*)&Ps[(qrow + g + 8) * PS_STRIDE + col] =
                make_float2(to_tf32(ex[nt][2] * f1), to_tf32(ex[nt][3] * f1));
        }

        if (kt + 1 < NKT) { CP_WAIT1(); } else { CP_WAIT0(); }
        __syncthreads();

#pragma unroll
        for (int k8 = 0; k8 < 8; k8++) {
            int kc = k8 * 8;
            uint32_t a0 = __float_as_uint(Ps[(qrow + g) * PS_STRIDE + kc + t]);
            uint32_t a1 = __float_as_uint(Ps[(qrow + g + 8) * PS_STRIDE + kc + t]);
            uint32_t a2 = __float_as_uint(Ps[(qrow + g) * PS_STRIDE + kc + t + 4]);
            uint32_t a3 = __float_as_uint(Ps[(qrow + g + 8) * PS_STRIDE + kc + t + 4]);
#pragma unroll
            for (int dt = 0; dt < 8; dt++) {
                int dv = nw * 64 + dt * 8 + g;
                uint32_t b0 = __float_as_uint(Vs[(kc + t) * VS_STRIDE + dv]);
                uint32_t b1 = __float_as_uint(Vs[(kc + t + 4) * VS_STRIDE + dv]);
                mma_tf32(o[dt], a0, a1, a2, a3, b0, b1);
            }
        }
    }

    float inv0 = 1.f / l0;
    float inv1 = 1.f / l1;
    int row0 = b * S_LEN + qt * 128 + qrow + g;
    int row1 = row0 + 8;
#pragma unroll
    for (int dt = 0; dt < 8; dt++) {
        int col = h * 128 + nw * 64 + dt * 8 + 2 * t;
        float2 v0 = make_float2(to_tf32(o[dt][0] * inv0), to_tf32(o[dt][1] * inv0));
        float2 v1 = make_float2(to_tf32(o[dt][2] * inv1), to_tf32(o[dt][3] * inv1));
        *(float2*)(attn + (size_t)row0 * 1024 + col) = v0;
        *(float2*)(attn + (size_t)row1 * 1024 + col) = v1;
    }
}

// ---------------- host launcher ----------------
extern "C" void kernel_launch(void* const* d_in, const int* in_sizes, int n_in,
                              void* d_out, int out_size)
{
    const float* x         = (const float*)d_in[0];
    const int*   pos       = (const int*)  d_in[1];
    const float* w_dq_w    = (const float*)d_in[2];
    const float* w_dq_b    = (const float*)d_in[3];
    const float* q_norm_w  = (const float*)d_in[4];
    const float* w_uq_qr_w = (const float*)d_in[5];
    const float* w_uq_qr_b = (const float*)d_in[6];
    const float* w_dkv_kr_w= (const float*)d_in[7];
    const float* w_dkv_kr_b= (const float*)d_in[8];
    const float* kv_norm_w = (const float*)d_in[9];
    const float* w_uk_uv_w = (const float*)d_in[10];
    const float* w_uk_uv_b = (const float*)d_in[11];
    const float* w_o_w     = (const float*)d_in[12];
    const float* w_o_b     = (const float*)d_in[13];
    float* out = (float*)d_out;

    float *cq, *ksb, *qsb, *attn;
    float *x32, *w13, *b13, *w2, *w4, *w5, *wqn, *bqn, *weff, *beff;
    cudaGetSymbolAddress((void**)&cq,   g_cq);
    cudaGetSymbolAddress((void**)&ksb,  g_ks);
    cudaGetSymbolAddress((void**)&qsb,  g_qs);
    cudaGetSymbolAddress((void**)&attn, g_attn);
    cudaGetSymbolAddress((void**)&x32,  g_x32);
    cudaGetSymbolAddress((void**)&w13,  g_w13);
    cudaGetSymbolAddress((void**)&b13,  g_b13);
    cudaGetSymbolAddress((void**)&w2,   g_w2);
    cudaGetSymbolAddress((void**)&w4,   g_w4);
    cudaGetSymbolAddress((void**)&w5,   g_w5);
    cudaGetSymbolAddress((void**)&wqn,  g_wqn);
    cudaGetSymbolAddress((void**)&bqn,  g_bqn);
    cudaGetSymbolAddress((void**)&weff, g_weff);
    cudaGetSymbolAddress((void**)&beff, g_beff);

    cudaFuncSetAttribute(flash_mma_kernel, cudaFuncAttributeMaxDynamicSharedMemorySize,
                         FLASH_SMEM_BYTES);
    cudaFuncSetAttribute(gemm_tf32_kernel, cudaFuncAttributeMaxDynamicSharedMemorySize,
                         GEMM_SMEM_BYTES);
    cudaFuncSetAttribute(gemm_cqkv_kernel, cudaFuncAttributeMaxDynamicSharedMemorySize,
                         GEMM_SMEM_BYTES);
    cudaFuncSetAttribute(gemm_qnew_kernel, cudaFuncAttributeMaxDynamicSharedMemorySize,
                         GEMM_SMEM_BYTES);
    cudaFuncSetAttribute(gemm_weff_kernel, cudaFuncAttributeMaxDynamicSharedMemorySize,
                         GEMM_SMEM_BYTES);

    round_all_kernel<<<(RA_TOTAL + 255) / 256, 256>>>(
        x, x32, w_uq_qr_w, w2, w_uk_uv_w, w4, w_o_w, w5,
        w_dq_w, w_dkv_kr_w, w13, w_dq_b, w_dkv_kr_b, b13);

    // precomputes (absorbed weights)
    precompute_wq_kernel<<<(128 * QN2 + 255) / 256, 256>>>(w2, w4, w_uq_qr_b, wqn, bqn);
    gemm_weff_kernel<<<dim3(8, 1, 8), 256, GEMM_SMEM_BYTES>>>(w4, w5, weff);
    precompute_beff_kernel<<<64, 256>>>(w_uk_uv_b, w_o_w, w_o_b, beff);

    dim3 blk(256);

    gemm_cqkv_kernel<<<dim3(3, NROWS / GBM), blk, GEMM_SMEM_BYTES>>>(
        x32, w13, b13, q_norm_w, kv_norm_w, pos, cq, ksb);

    gemm_qnew_kernel<<<dim3(QN2 / GBN, NROWS / GBM), blk, GEMM_SMEM_BYTES>>>(
        cq, wqn, bqn, pos, qsb);

    flash_mma_kernel<<<dim3(S_LEN / 128, NH, BATCH), 512, FLASH_SMEM_BYTES>>>(qsb, ksb, attn);

    gemm_tf32_kernel<<<dim3(1024 / GBN, NROWS / GBM), blk, GEMM_SMEM_BYTES>>>(
        attn, 1024, weff, beff, out, NROWS, 1024, 1024);
}

// round 14
// speedup vs baseline: 1.1427x; 1.0140x over previous
#include <cuda_runtime.h>
#include <math.h>
#include <stdint.h>

// ---------------- problem constants ----------------
#define BATCH   2
#define S_LEN   2048
#define NROWS   (BATCH * S_LEN)     // 4096
#define DIM_    1024
#define NH      8
#define SM_SCALE 0.08838834764831845f   // 1/sqrt(128)
#define CQKV_N  384                      // 128 (cq) + 192 (ckv_kr) + 64 pad
#define KD2     192                      // absorbed K dim: 128 ckv + 64 rope
#define QN2     1536                     // 8 heads * 192

// ---------------- scratch ----------------
__device__ float g_cq   [(size_t)NROWS * 128];
__device__ float g_ks   [(size_t)NROWS * KD2];               // [b,s,192] head-shared
__device__ float g_qs   [(size_t)BATCH * NH * S_LEN * KD2];  // [b,h,s,192]
__device__ float g_attn [(size_t)NROWS * 1024];              // P@ckv concat heads
__device__ float g_x32  [(size_t)NROWS * DIM_];
__device__ float g_w13  [(size_t)DIM_ * CQKV_N];
__device__ float g_b13  [CQKV_N];
__device__ float g_w2   [(size_t)128 * 1024];
__device__ float g_w4   [(size_t)128 * 2560];
__device__ float g_w5   [(size_t)2048 * DIM_];
__device__ float g_wqn  [(size_t)128 * QN2];                 // absorbed q weights
__device__ float g_bqn  [QN2];
__device__ float g_weff [(size_t)1024 * 1024];               // W_uv @ W_o
__device__ float g_beff [1024];

// ---------------- helpers ----------------
__device__ __forceinline__ float to_tf32(float x) {
    uint32_t u;
    asm("cvt.rna.tf32.f32 %0, %1;" : "=r"(u) : "f"(x));
    return __uint_as_float(u);
}

__device__ __forceinline__ void mma_tf32(float* c, uint32_t a0, uint32_t a1,
                                         uint32_t a2, uint32_t a3,
                                         uint32_t b0, uint32_t b1) {
    asm volatile(
        "mma.sync.aligned.m16n8k8.row.col.f32.tf32.tf32.f32 "
        "{%0,%1,%2,%3}, {%4,%5,%6,%7}, {%8,%9}, {%0,%1,%2,%3};"
        : "+f"(c[0]), "+f"(c[1]), "+f"(c[2]), "+f"(c[3])
        : "r"(a0), "r"(a1), "r"(a2), "r"(a3), "r"(b0), "r"(b1));
}

__device__ __forceinline__ void cp_async16(void* smem_ptr, const void* gptr) {
    uint32_t s = (uint32_t)__cvta_generic_to_shared(smem_ptr);
    asm volatile("cp.async.cg.shared.global [%0], [%1], 16;" :: "r"(s), "l"(gptr));
}
#define CP_COMMIT() asm volatile("cp.async.commit_group;")
#define CP_WAIT0()  asm volatile("cp.async.wait_group 0;")
#define CP_WAIT1()  asm volatile("cp.async.wait_group 1;")

// ---------------- tf32 rounding / w13 packing ----------------
#define RA_X   1048576
#define RA_W2  (RA_X  + 32768)
#define RA_W4  (RA_W2 + 81920)
#define RA_W5  (RA_W4 + 524288)
#define RA_W13 (RA_W5 + 98304)
#define RA_B13 (RA_W13 + 96)
#define RA_TOTAL RA_B13

__global__ __launch_bounds__(256)
void round_all_kernel(const float* __restrict__ x,    float* __restrict__ ox,
                      const float* __restrict__ w2i,  float* __restrict__ w2o,
                      const float* __restrict__ w4i,  float* __restrict__ w4o,
                      const float* __restrict__ w5i,  float* __restrict__ w5o,
                      const float* __restrict__ w1i,  const float* __restrict__ w3i,
                      float* __restrict__ w13o,
                      const float* __restrict__ b1i,  const float* __restrict__ b3i,
                      float* __restrict__ b13o)
{
    int i = blockIdx.x * 256 + threadIdx.x;
    if (i >= RA_TOTAL) return;
    float4 v;
    float4* dst;
    if (i < RA_X)       { v = ((const float4*)x)[i];             dst = (float4*)ox  + i; }
    else if (i < RA_W2) { int o = i - RA_X;  v = ((const float4*)w2i)[o]; dst = (float4*)w2o + o; }
    else if (i < RA_W4) { int o = i - RA_W2; v = ((const float4*)w4i)[o]; dst = (float4*)w4o + o; }
    else if (i < RA_W5) { int o = i - RA_W4; v = ((const float4*)w5i)[o]; dst = (float4*)w5o + o; }
    else if (i < RA_W13) {
        int o = i - RA_W5;
        int k = o / 96, c4 = (o % 96) * 4;
        if (c4 < 128)      v = *(const float4*)(w1i + (size_t)k * 128 + c4);
        else if (c4 < 320) v = *(const float4*)(w3i + (size_t)k * 192 + (c4 - 128));
        else               v = make_float4(0.f, 0.f, 0.f, 0.f);
        dst = (float4*)w13o + o;
    } else {
        int o = i - RA_W13;
        int c4 = o * 4;
        if (c4 < 128)      v = *(const float4*)(b1i + c4);
        else if (c4 < 320) v = *(const float4*)(b3i + (c4 - 128));
        else               v = make_float4(0.f, 0.f, 0.f, 0.f);
        *(float4*)(b13o + c4) = v;
        return;
    }
    v.x = to_tf32(v.x); v.y = to_tf32(v.y);
    v.z = to_tf32(v.z); v.w = to_tf32(v.w);
    *dst = v;
}

// ---------------- absorbed q-weight precompute ----------------
__global__ __launch_bounds__(256)
void precompute_wq_kernel(const float* __restrict__ w2r, const float* __restrict__ w4r,
                          const float* __restrict__ b2,  float* __restrict__ wqn,
                          float* __restrict__ bqn)
{
    int idx = blockIdx.x * 256 + threadIdx.x;
    if (idx >= 128 * QN2) return;
    int r = idx / QN2;
    int c = idx % QN2;
    int h = c / KD2;
    int j = c - h * KD2;
    float val, bv = 0.f;
    if (j < 128) {
        float s = 0.f, bs = 0.f;
        const float* w2p = w2r + (size_t)r * 1024 + h * 96;
        const float* w4p = w4r + (size_t)j * 2560 + h * 64;
        const float* b2p = b2 + h * 96;
#pragma unroll 8
        for (int d = 0; d < 64; d++) {
            s  += w2p[d] * w4p[d];
            bs += b2p[d] * w4p[d];
        }
        val = to_tf32(s);
        bv = bs;
    } else if (j < 160) {
        val = w2r[(size_t)r * 1024 + h * 96 + 64 + (j - 128)];
        bv  = b2[h * 96 + 64 + (j - 128)];
    } else {
        val = w2r[(size_t)r * 1024 + 768 + h * 32 + (j - 160)];
        bv  = b2[768 + h * 32 + (j - 160)];
    }
    wqn[(size_t)r * QN2 + c] = val;
    if (r == 0) bqn[c] = bv;
}

// ---------------- b_eff = b_o + b_v @ W_o (high-occupancy reduction) ----------------
// 256 blocks x 256 threads; block owns 4 j-cols; 64 r-chunks of 32 rows per col.
__global__ __launch_bounds__(256)
void precompute_beff_kernel(const float* __restrict__ b45, const float* __restrict__ w_o,
                            const float* __restrict__ b_o, float* __restrict__ beff)
{
    __shared__ float red[256];
    int jb = blockIdx.x * 4;
    int tj = threadIdx.x & 3;
    int tr = threadIdx.x >> 2;         // 0..63
    int j = jb + tj;
    float s = 0.f;
    int r0 = tr * 32;
#pragma unroll 8
    for (int r = r0; r < r0 + 32; r++)
        s += b45[512 + r] * w_o[(size_t)r * 1024 + j];
    red[threadIdx.x] = s;
    __syncthreads();
    if (threadIdx.x < 4) {
        float acc = b_o[jb + threadIdx.x];
#pragma unroll
        for (int k = 0; k < 64; k++) acc += red[k * 4 + threadIdx.x];
        beff[jb + threadIdx.x] = acc;
    }
}

// ================= TF32 GEMM core (CTA 128x128, BK=32, 256 thr) =================
#define GBM 128
#define GBN 128
#define GBK 32
#define AS_STRIDE 36
#define BS_STRIDE 136
#define ABUF (GBM * AS_STRIDE)
#define BBUF (GBK * BS_STRIDE)
#define GEMM_SMEM_FLOATS (2 * (ABUF + BBUF))
#define GEMM_SMEM_BYTES  (GEMM_SMEM_FLOATS * 4)

#define GEMM_MAINLOOP(A, lda, B, N, K, m0, n0)                                        \
    float acc[2][8][4];                                                               \
    _Pragma("unroll") for (int mi = 0; mi < 2; mi++)                                  \
    _Pragma("unroll") for (int ni = 0; ni < 8; ni++)                                  \
    _Pragma("unroll") for (int j = 0; j < 4; j++) acc[mi][ni][j] = 0.f;               \
    int nk = (K) / GBK;                                                               \
    auto load_tile = [&](int kt, int bufi) {                                          \
        float* As_ = sm + bufi * (ABUF + BBUF);                                       \
        float* Bs_ = As_ + ABUF;                                                      \
        int k0 = kt * GBK;                                                            \
        _Pragma("unroll") for (int p = 0; p < 4; p++) {                               \
            int idx = tid + p * 256;                                                  \
            int r = idx >> 3, c = (idx & 7) * 4;                                      \
            cp_async16(&As_[r * AS_STRIDE + c], (A) + (size_t)((m0) + r) * (lda) + k0 + c); \
        }                                                                             \
        _Pragma("unroll") for (int p = 0; p < 4; p++) {                               \
            int idx = tid + p * 256;                                                  \
            int r = idx >> 5, c = (idx & 31) * 4;                                     \
            cp_async16(&Bs_[r * BS_STRIDE + c], (B) + (size_t)(k0 + r) * (N) + (n0) + c); \
        }                                                                             \
        CP_COMMIT();                                                                  \
    };                                                                                \
    load_tile(0, 0);                                                                  \
    for (int kt = 0; kt < nk; kt++) {                                                 \
        int bufi = kt & 1;                                                            \
        if (kt + 1 < nk) { load_tile(kt + 1, bufi ^ 1); CP_WAIT1(); }                 \
        else            { CP_WAIT0(); }                                               \
        __syncthreads();                                                              \
        const float* As_ = sm + bufi * (ABUF + BBUF);                                 \
        const float* Bs_ = As_ + ABUF;                                                \
        _Pragma("unroll") for (int k8 = 0; k8 < 4; k8++) {                            \
            int kc = k8 * 8;                                                          \
            uint32_t a[2][4];                                                         \
            _Pragma("unroll") for (int mi = 0; mi < 2; mi++) {                        \
                int row = wm * 32 + mi * 16;                                          \
                a[mi][0] = __float_as_uint(As_[(row + g) * AS_STRIDE + kc + t]);      \
                a[mi][1] = __float_as_uint(As_[(row + g + 8) * AS_STRIDE + kc + t]);  \
                a[mi][2] = __float_as_uint(As_[(row + g) * AS_STRIDE + kc + t + 4]);  \
                a[mi][3] = __float_as_uint(As_[(row + g + 8) * AS_STRIDE + kc + t + 4]); \
            }                                                                         \
            _Pragma("unroll") for (int ni = 0; ni < 8; ni++) {                        \
                int col = wn * 64 + ni * 8 + g;                                       \
                uint32_t b0 = __float_as_uint(Bs_[(kc + t) * BS_STRIDE + col]);       \
                uint32_t b1 = __float_as_uint(Bs_[(kc + t + 4) * BS_STRIDE + col]);   \
                mma_tf32(acc[0][ni], a[0][0], a[0][1], a[0][2], a[0][3], b0, b1);     \
                mma_tf32(acc[1][ni], a[1][0], a[1][1], a[1][2], a[1][3], b0, b1);     \
            }                                                                         \
        }                                                                             \
        __syncthreads();                                                              \
    }

#define GEMM_PREAMBLE                  \
    extern __shared__ float sm[];      \
    int tid  = threadIdx.x;            \
    int wid  = tid >> 5;               \
    int lane = tid & 31;               \
    int wm = wid >> 1;                 \
    int wn = wid & 1;                  \
    int g  = lane >> 2;                \
    int t  = lane & 3;

// ---------------- plain GEMM + bias, fp32 out ----------------
__global__ __launch_bounds__(256, 2)
void gemm_tf32_kernel(const float* __restrict__ A, int lda,
                      const float* __restrict__ B,
                      const float* __restrict__ bias,
                      float* __restrict__ C,
                      int M, int N, int K)
{
    GEMM_PREAMBLE
    int m0 = blockIdx.y * GBM;
    int n0 = blockIdx.x * GBN;
    GEMM_MAINLOOP(A, lda, B, N, K, m0, n0)

#pragma unroll
    for (int ni = 0; ni < 8; ni++) {
        int col = n0 + wn * 64 + ni * 8 + 2 * t;
        float2 bv = *(const float2*)(bias + col);
#pragma unroll
        for (int mi = 0; mi < 2; mi++) {
            int r0 = m0 + wm * 32 + mi * 16 + g;
            float2 v0 = make_float2(acc[mi][ni][0] + bv.x, acc[mi][ni][1] + bv.y);
            float2 v1 = make_float2(acc[mi][ni][2] + bv.x, acc[mi][ni][3] + bv.y);
            *(float2*)(C + (size_t)r0 * N + col) = v0;
            *(float2*)(C + (size_t)(r0 + 8) * N + col) = v1;
        }
    }
}

// ---------------- W_eff batched GEMM: W_eff_h = W_uv_h @ W_o_h ----------------
__global__ __launch_bounds__(256, 2)
void gemm_weff_kernel(const float* __restrict__ w4r, const float* __restrict__ w5r,
                      float* __restrict__ weff)
{
    GEMM_PREAMBLE
    int h = blockIdx.z;
    int m0 = 0;
    int n0 = blockIdx.x * GBN;
    const float* A = w4r + 512 + h * 256;
    const float* B = w5r + (size_t)h * 256 * 1024;
    GEMM_MAINLOOP(A, 2560, B, 1024, 256, m0, n0)

#pragma unroll
    for (int ni = 0; ni < 8; ni++) {
        int col = n0 + wn * 64 + ni * 8 + 2 * t;
#pragma unroll
        for (int mi = 0; mi < 2; mi++) {
            int r0 = h * 128 + wm * 32 + mi * 16 + g;
            float2 v0 = make_float2(to_tf32(acc[mi][ni][0]), to_tf32(acc[mi][ni][1]));
            float2 v1 = make_float2(to_tf32(acc[mi][ni][2]), to_tf32(acc[mi][ni][3]));
            *(float2*)(weff + (size_t)r0 * 1024 + col) = v0;
            *(float2*)(weff + (size_t)(r0 + 8) * 1024 + col) = v1;
        }
    }
}

// ---------------- cqkv GEMM (A = pre-rounded x32) ----------------
#define STG_STRIDE 129
__global__ __launch_bounds__(256, 2)
void gemm_cqkv_kernel(const float* __restrict__ A,
                      const float* __restrict__ B,
                      const float* __restrict__ bias,
                      const float* __restrict__ wq_norm,
                      const float* __restrict__ wkv_norm,
                      const int* __restrict__ pos,
                      float* __restrict__ cq,
                      float* __restrict__ ks)
{
    GEMM_PREAMBLE
    int m0 = blockIdx.y * GBM;
    int tileN = blockIdx.x;            // 0,1,2
    int n0 = tileN * GBN;
    GEMM_MAINLOOP(A, DIM_, B, CQKV_N, DIM_, m0, n0)

    if (tileN < 2) {
        float* stage = sm;
        float* scl   = sm + 128 * STG_STRIDE;
#pragma unroll
        for (int ni = 0; ni < 8; ni++) {
            int col = wn * 64 + ni * 8 + 2 * t;
            float2 bv = *(const float2*)(bias + n0 + col);
#pragma unroll
            for (int mi = 0; mi < 2; mi++) {
#pragma unroll
                for (int hf = 0; hf < 2; hf++) {
                    int rowl = wm * 32 + mi * 16 + g + hf * 8;
                    stage[rowl * STG_STRIDE + col]     = acc[mi][ni][hf * 2 + 0] + bv.x;
                    stage[rowl * STG_STRIDE + col + 1] = acc[mi][ni][hf * 2 + 1] + bv.y;
                }
            }
        }
        __syncthreads();
        if (tid < 128) {
            const float* rp = stage + tid * STG_STRIDE;
            float ssq = 0.f;
#pragma unroll 16
            for (int c = 0; c < 128; c++) ssq += rp[c] * rp[c];
            scl[tid] = rsqrtf(ssq * (1.f / 128.f) + 1e-8f);
        }
        __syncthreads();
        const float* w = (tileN == 0) ? wq_norm : wkv_norm;
        for (int idx = tid; idx < 128 * 128; idx += 256) {
            int row = idx >> 7, col = idx & 127;
            float v = to_tf32(stage[row * STG_STRIDE + col] * w[col] * scl[row]);
            if (tileN == 0) cq[(size_t)(m0 + row) * 128 + col] = v;
            else            ks[(size_t)(m0 + row) * KD2 + col] = v;
        }
    } else {
        if (wn == 0) {
#pragma unroll
            for (int ni = 0; ni < 8; ni++) {
                int col = ni * 8 + 2 * t;
                float2 bv = *(const float2*)(bias + n0 + col);
                int i = col >> 1;
                float inv = powf(10000.f, -(float)(2 * i) / 64.f);
#pragma unroll
                for (int mi = 0; mi < 2; mi++) {
#pragma unroll
                    for (int hf = 0; hf < 2; hf++) {
                        int row = m0 + wm * 32 + mi * 16 + g + hf * 8;
                        float xe = acc[mi][ni][hf * 2 + 0] + bv.x;
                        float xo = acc[mi][ni][hf * 2 + 1] + bv.y;
                        float ang = (float)pos[row] * inv;
                        float sn, cs;
                        sincosf(ang, &sn, &cs);
                        float* dst = ks + (size_t)row * KD2 + 128 + 2 * i;
                        dst[0] = to_tf32(xe * cs - xo * sn);
                        dst[1] = to_tf32(xe * sn + xo * cs);
                    }
                }
            }
        }
    }
}

// ---------------- absorbed q GEMM: qs[b,h,s,192] ----------------
__global__ __launch_bounds__(256, 2)
void gemm_qnew_kernel(const float* __restrict__ A,
                      const float* __restrict__ B,
                      const float* __restrict__ bias,
                      const int* __restrict__ pos,
                      float* __restrict__ qs)
{
    GEMM_PREAMBLE
    int m0 = blockIdx.y * GBM;
    int n0 = blockIdx.x * GBN;
    GEMM_MAINLOOP(A, 128, B, QN2, 128, m0, n0)

#pragma unroll
    for (int ni = 0; ni < 8; ni++) {
        int col = n0 + wn * 64 + ni * 8 + 2 * t;
        float2 bv = *(const float2*)(bias + col);
        int h = col / KD2;
        int j = col - h * KD2;
#pragma unroll
        for (int mi = 0; mi < 2; mi++) {
#pragma unroll
            for (int hf = 0; hf < 2; hf++) {
                int row = m0 + wm * 32 + mi * 16 + g + hf * 8;
                float c0 = acc[mi][ni][hf * 2 + 0] + bv.x;
                float c1 = acc[mi][ni][hf * 2 + 1] + bv.y;
                float o0, o1;
                if (j < 160) {
                    o0 = c0; o1 = c1;
                } else {
                    int i = (j - 160) >> 1;
                    float ang = (float)pos[row] * powf(10000.f, -(float)(2 * i) / 32.f);
                    float sn, cs;
                    sincosf(ang, &sn, &cs);
                    o0 = c0 * cs - c1 * sn;
                    o1 = c0 * sn + c1 * cs;
                }
                int b = row >> 11, s = row & 2047;
                float* dst = qs + (((size_t)(b * 8 + h) * 2048 + s) * KD2 + j);
                dst[0] = to_tf32(o0 * SM_SCALE);
                dst[1] = to_tf32(o1 * SM_SCALE);
            }
        }
    }
}

// ---------------- absorbed flash attention ----------------
#define QS_STRIDE 196
#define KS_STRIDE 196
#define VS_STRIDE 136
#define PS_STRIDE 68
#define QS_OFF  0
#define KS_OFF  (QS_OFF + 128 * QS_STRIDE)
#define VS_OFF  (KS_OFF + 64 * KS_STRIDE)
#define PS_OFF  (VS_OFF + 64 * VS_STRIDE)
#define STM_OFF (PS_OFF + 128 * PS_STRIDE)
#define STS_OFF (STM_OFF + 256)
#define FLASH_SMEM_FLOATS (STS_OFF + 256)
#define FLASH_SMEM_BYTES  (FLASH_SMEM_FLOATS * 4)
#define NKT (S_LEN / 64)

__global__ __launch_bounds__(512, 1)
void flash_mma_kernel(const float* __restrict__ qs, const float* __restrict__ ks,
                      float* __restrict__ attn)
{
    extern __shared__ float sm[];
    float* Qs  = sm + QS_OFF;
    float* Ks  = sm + KS_OFF;
    float* Vs  = sm + VS_OFF;
    float* Ps  = sm + PS_OFF;
    float* StM = sm + STM_OFF;
    float* StS = sm + STS_OFF;

    int b = blockIdx.z, h = blockIdx.y, qt = blockIdx.x;
    int tid  = threadIdx.x;
    int wid  = tid >> 5;
    int lane = tid & 31;
    int mw = wid >> 1;
    int nw = wid & 1;
    int g  = lane >> 2;
    int t  = lane & 3;

    size_t bh = (size_t)(b * NH + h) * S_LEN;
    const float* Kbase = ks + (size_t)b * S_LEN * KD2;

    auto load_k_tile = [&](int kt) {
        const float* Kg = Kbase + (size_t)kt * 64 * KD2;
#pragma unroll
        for (int p = 0; p < 6; p++) {
            int idx = tid + p * 512;
            int r = idx / 48, c = (idx % 48) * 4;
            cp_async16(&Ks[r * KS_STRIDE + c], Kg + r * KD2 + c);
        }
        CP_COMMIT();
    };
    auto load_v_tile = [&](int kt) {
        const float* Kg = Kbase + (size_t)kt * 64 * KD2;
#pragma unroll
        for (int p = 0; p < 4; p++) {
            int idx = tid + p * 512;
            int r = idx >> 5, c = (idx & 31) * 4;
            cp_async16(&Vs[r * VS_STRIDE + c], Kg + r * KD2 + c);
        }
        CP_COMMIT();
    };

    load_k_tile(0);
    {
        const float4* Qg = (const float4*)(qs + (bh + (size_t)qt * 128) * KD2);
#pragma unroll
        for (int p = 0; p < 12; p++) {
            int idx = tid + p * 512;
            int r = idx / 48, c4 = idx % 48;
            *(float4*)&Qs[r * QS_STRIDE + c4 * 4] = Qg[r * 48 + c4];
        }
    }

    int qrow = mw * 16;
    float m0 = -1e30f, m1 = -1e30f, l0 = 0.f, l1 = 0.f;
    float o[8][4];
#pragma unroll
    for (int dt = 0; dt < 8; dt++)
#pragma unroll
        for (int j = 0; j < 4; j++) o[dt][j] = 0.f;

    for (int kt = 0; kt < NKT; kt++) {
        CP_WAIT0();
        __syncthreads();

        load_v_tile(kt);

        float c[4][4];
#pragma unroll
        for (int nt = 0; nt < 4; nt++)
#pragma unroll
            for (int j = 0; j < 4; j++) c[nt][j] = 0.f;

#pragma unroll
        for (int k8 = 0; k8 < 24; k8++) {
            int kc = k8 * 8;
            uint32_t a0 = __float_as_uint(Qs[(qrow + g) * QS_STRIDE + kc + t]);
            uint32_t a1 = __float_as_uint(Qs[(qrow + g + 8) * QS_STRIDE + kc + t]);
            uint32_t a2 = __float_as_uint(Qs[(qrow + g) * QS_STRIDE + kc + t + 4]);
            uint32_t a3 = __float_as_uint(Qs[(qrow + g + 8) * QS_STRIDE + kc + t + 4]);
#pragma unroll
            for (int nt = 0; nt < 4; nt++) {
                int ncol = nw * 32 + nt * 8 + g;
                uint32_t b0 = __float_as_uint(Ks[ncol * KS_STRIDE + kc + t]);
                uint32_t b1 = __float_as_uint(Ks[ncol * KS_STRIDE + kc + t + 4]);
                mma_tf32(c[nt], a0, a1, a2, a3, b0, b1);
            }
        }

        float pm0 = -1e30f, pm1 = -1e30f;
#pragma unroll
        for (int nt = 0; nt < 4; nt++) {
            pm0 = fmaxf(pm0, fmaxf(c[nt][0], c[nt][1]));
            pm1 = fmaxf(pm1, fmaxf(c[nt][2], c[nt][3]));
        }
        pm0 = fmaxf(pm0, __shfl_xor_sync(0xffffffffu, pm0, 1));
        pm0 = fmaxf(pm0, __shfl_xor_sync(0xffffffffu, pm0, 2));
        pm1 = fmaxf(pm1, __shfl_xor_sync(0xffffffffu, pm1, 1));
        pm1 = fmaxf(pm1, __shfl_xor_sync(0xffffffffu, pm1, 2));

        float ex[4][4];
        float ps0 = 0.f, ps1 = 0.f;
#pragma unroll
        for (int nt = 0; nt < 4; nt++) {
            ex[nt][0] = __expf(c[nt][0] - pm0);
            ex[nt][1] = __expf(c[nt][1] - pm0);
            ex[nt][2] = __expf(c[nt][2] - pm1);
            ex[nt][3] = __expf(c[nt][3] - pm1);
            ps0 += ex[nt][0] + ex[nt][1];
            ps1 += ex[nt][2] + ex[nt][3];
        }
        ps0 += __shfl_xor_sync(0xffffffffu, ps0, 1);
        ps0 += __shfl_xor_sync(0xffffffffu, ps0, 2);
        ps1 += __shfl_xor_sync(0xffffffffu, ps1, 1);
        ps1 += __shfl_xor_sync(0xffffffffu, ps1, 2);

        if (t == 0) {
            StM[nw * 128 + qrow + g]     = pm0;
            StM[nw * 128 + qrow + g + 8] = pm1;
            StS[nw * 128 + qrow + g]     = ps0;
            StS[nw * 128 + qrow + g + 8] = ps1;
        }
        __syncthreads();

        if (kt + 1 < NKT) load_k_tile(kt + 1);

        int ow = 1 - nw;
        float pmO0 = StM[ow * 128 + qrow + g];
        float pmO1 = StM[ow * 128 + qrow + g + 8];
        float psO0 = StS[ow * 128 + qrow + g];
        float psO1 = StS[ow * 128 + qrow + g + 8];

        float mn0 = fmaxf(pm0, pmO0);
        float mn1 = fmaxf(pm1, pmO1);
        float rs0 = ps0 * __expf(pm0 - mn0) + psO0 * __expf(pmO0 - mn0);
        float rs1 = ps1 * __expf(pm1 - mn1) + psO1 * __expf(pmO1 - mn1);

        float mnew0 = fmaxf(m0, mn0);
        float mnew1 = fmaxf(m1, mn1);
        float corr0 = __expf(m0 - mnew0);
        float corr1 = __expf(m1 - mnew1);
        l0 = l0 * corr0 + rs0 * __expf(mn0 - mnew0);
        l1 = l1 * corr1 + rs1 * __expf(mn1 - mnew1);
        m0 = mnew0;
        m1 = mnew1;

#pragma unroll
        for (int dt = 0; dt < 8; dt++) {
            o[dt][0] *= corr0;
            o[dt][1] *= corr0;
            o[dt][2] *= corr1;
            o[dt][3] *= corr1;
        }

        float f0 = __expf(pm0 - mnew0);
        float f1 = __expf(pm1 - mnew1);
#pragma unroll
        for (int nt = 0; nt < 4; nt++) {
            int col = nw * 32 + nt * 8 + 2 * t;
            *(float2*)&Ps[(qrow + g) * PS_STRIDE + col] =
                make_float2(to_tf32(ex[nt][0] * f0), to_tf32(ex[nt][1] * f0));
            *(float2*)&Ps[(qrow + g + 8) * PS_STRIDE + col] =
                make_float2(to_tf32(ex[nt][2] * f1), to_tf32(ex[nt][3] * f1));
        }

        if (kt + 1 < NKT) { CP_WAIT1(); } else { CP_WAIT0(); }
        __syncthreads();

#pragma unroll
        for (int k8 = 0; k8 < 8; k8++) {
            int kc = k8 * 8;
            uint32_t a0 = __float_as_uint(Ps[(qrow + g) * PS_STRIDE + kc + t]);
            uint32_t a1 = __float_as_uint(Ps[(qrow + g + 8) * PS_STRIDE + kc + t]);
            uint32_t a2 = __float_as_uint(Ps[(qrow + g) * PS_STRIDE + kc + t + 4]);
            uint32_t a3 = __float_as_uint(Ps[(qrow + g + 8) * PS_STRIDE + kc + t + 4]);
#pragma unroll
            for (int dt = 0; dt < 8; dt++) {
                int dv = nw * 64 + dt * 8 + g;
                uint32_t b0 = __float_as_uint(Vs[(kc + t) * VS_STRIDE + dv]);
                uint32_t b1 = __float_as_uint(Vs[(kc + t + 4) * VS_STRIDE + dv]);
                mma_tf32(o[dt], a0, a1, a2, a3, b0, b1);
            }
        }
    }

    float inv0 = 1.f / l0;
    float inv1 = 1.f / l1;
    int row0 = b * S_LEN + qt * 128 + qrow + g;
    int row1 = row0 + 8;
#pragma unroll
    for (int dt = 0; dt < 8; dt++) {
        int col = h * 128 + nw * 64 + dt * 8 + 2 * t;
        float2 v0 = make_float2(to_tf32(o[dt][0] * inv0), to_tf32(o[dt][1] * inv0));
        float2 v1 = make_float2(to_tf32(o[dt][2] * inv1), to_tf32(o[dt][3] * inv1));
        *(float2*)(attn + (size_t)row0 * 1024 + col) = v0;
        *(float2*)(attn + (size_t)row1 * 1024 + col) = v1;
    }
}

// ---------------- host launcher ----------------
extern "C" void kernel_launch(void* const* d_in, const int* in_sizes, int n_in,
                              void* d_out, int out_size)
{
    const float* x         = (const float*)d_in[0];
    const int*   pos       = (const int*)  d_in[1];
    const float* w_dq_w    = (const float*)d_in[2];
    const float* w_dq_b    = (const float*)d_in[3];
    const float* q_norm_w  = (const float*)d_in[4];
    const float* w_uq_qr_w = (const float*)d_in[5];
    const float* w_uq_qr_b = (const float*)d_in[6];
    const float* w_dkv_kr_w= (const float*)d_in[7];
    const float* w_dkv_kr_b= (const float*)d_in[8];
    const float* kv_norm_w = (const float*)d_in[9];
    const float* w_uk_uv_w = (const float*)d_in[10];
    const float* w_uk_uv_b = (const float*)d_in[11];
    const float* w_o_w     = (const float*)d_in[12];
    const float* w_o_b     = (const float*)d_in[13];
    float* out = (float*)d_out;

    float *cq, *ksb, *qsb, *attn;
    float *x32, *w13, *b13, *w2, *w4, *w5, *wqn, *bqn, *weff, *beff;
    cudaGetSymbolAddress((void**)&cq,   g_cq);
    cudaGetSymbolAddress((void**)&ksb,  g_ks);
    cudaGetSymbolAddress((void**)&qsb,  g_qs);
    cudaGetSymbolAddress((void**)&attn, g_attn);
    cudaGetSymbolAddress((void**)&x32,  g_x32);
    cudaGetSymbolAddress((void**)&w13,  g_w13);
    cudaGetSymbolAddress((void**)&b13,  g_b13);
    cudaGetSymbolAddress((void**)&w2,   g_w2);
    cudaGetSymbolAddress((void**)&w4,   g_w4);
    cudaGetSymbolAddress((void**)&w5,   g_w5);
    cudaGetSymbolAddress((void**)&wqn,  g_wqn);
    cudaGetSymbolAddress((void**)&bqn,  g_bqn);
    cudaGetSymbolAddress((void**)&weff, g_weff);
    cudaGetSymbolAddress((void**)&beff, g_beff);

    cudaFuncSetAttribute(flash_mma_kernel, cudaFuncAttributeMaxDynamicSharedMemorySize,
                         FLASH_SMEM_BYTES);
    cudaFuncSetAttribute(gemm_tf32_kernel, cudaFuncAttributeMaxDynamicSharedMemorySize,
                         GEMM_SMEM_BYTES);
    cudaFuncSetAttribute(gemm_cqkv_kernel, cudaFuncAttributeMaxDynamicSharedMemorySize,
                         GEMM_SMEM_BYTES);
    cudaFuncSetAttribute(gemm_qnew_kernel, cudaFuncAttributeMaxDynamicSharedMemorySize,
                         GEMM_SMEM_BYTES);
    cudaFuncSetAttribute(gemm_weff_kernel, cudaFuncAttributeMaxDynamicSharedMemorySize,
                         GEMM_SMEM_BYTES);

    round_all_kernel<<<(RA_TOTAL + 255) / 256, 256>>>(
        x, x32, w_uq_qr_w, w2, w_uk_uv_w, w4, w_o_w, w5,
        w_dq_w, w_dkv_kr_w, w13, w_dq_b, w_dkv_kr_b, b13);

    // precomputes (absorbed weights)
    precompute_wq_kernel<<<(128 * QN2 + 255) / 256, 256>>>(w2, w4, w_uq_qr_b, wqn, bqn);
    gemm_weff_kernel<<<dim3(8, 1, 8), 256, GEMM_SMEM_BYTES>>>(w4, w5, weff);
    precompute_beff_kernel<<<256, 256>>>(w_uk_uv_b, w_o_w, w_o_b, beff);

    dim3 blk(256);

    gemm_cqkv_kernel<<<dim3(3, NROWS / GBM), blk, GEMM_SMEM_BYTES>>>(
        x32, w13, b13, q_norm_w, kv_norm_w, pos, cq, ksb);

    gemm_qnew_kernel<<<dim3(QN2 / GBN, NROWS / GBM), blk, GEMM_SMEM_BYTES>>>(
        cq, wqn, bqn, pos, qsb);

    flash_mma_kernel<<<dim3(S_LEN / 128, NH, BATCH), 512, FLASH_SMEM_BYTES>>>(qsb, ksb, attn);

    gemm_tf32_kernel<<<dim3(1024 / GBN, NROWS / GBM), blk, GEMM_SMEM_BYTES>>>(
        attn, 1024, weff, beff, out, NROWS, 1024, 1024);
}

// round 16
// speedup vs baseline: 1.1604x; 1.0155x over previous
#include <cuda_runtime.h>
#include <math.h>
#include <stdint.h>

// ---------------- problem constants ----------------
#define BATCH   2
#define S_LEN   2048
#define NROWS   (BATCH * S_LEN)     // 4096
#define DIM_    1024
#define NH      8
#define SM_SCALE 0.08838834764831845f   // 1/sqrt(128)
#define CQKV_N  384                      // 128 (cq) + 192 (ckv_kr) + 64 pad
#define KD2     192                      // absorbed K dim: 128 ckv + 64 rope
#define QN2     1536                     // 8 heads * 192

// ---------------- scratch ----------------
__device__ float g_cq   [(size_t)NROWS * 128];
__device__ float g_ks   [(size_t)NROWS * KD2];               // [b,s,192] head-shared
__device__ float g_qs   [(size_t)BATCH * NH * S_LEN * KD2];  // [b,h,s,192]
__device__ float g_attn [(size_t)NROWS * 1024];              // P@ckv concat heads
__device__ float g_x32  [(size_t)NROWS * DIM_];
__device__ float g_w13  [(size_t)DIM_ * CQKV_N];
__device__ float g_b13  [CQKV_N];
__device__ float g_wqn  [(size_t)128 * QN2];                 // absorbed q weights
__device__ float g_bqn  [QN2];
__device__ float g_weff [(size_t)1024 * 1024];               // W_uv @ W_o
__device__ float g_beff [1024];

// ---------------- helpers ----------------
__device__ __forceinline__ float to_tf32(float x) {
    uint32_t u;
    asm("cvt.rna.tf32.f32 %0, %1;" : "=r"(u) : "f"(x));
    return __uint_as_float(u);
}

__device__ __forceinline__ void mma_tf32(float* c, uint32_t a0, uint32_t a1,
                                         uint32_t a2, uint32_t a3,
                                         uint32_t b0, uint32_t b1) {
    asm volatile(
        "mma.sync.aligned.m16n8k8.row.col.f32.tf32.tf32.f32 "
        "{%0,%1,%2,%3}, {%4,%5,%6,%7}, {%8,%9}, {%0,%1,%2,%3};"
        : "+f"(c[0]), "+f"(c[1]), "+f"(c[2]), "+f"(c[3])
        : "r"(a0), "r"(a1), "r"(a2), "r"(a3), "r"(b0), "r"(b1));
}

__device__ __forceinline__ void cp_async16(void* smem_ptr, const void* gptr) {
    uint32_t s = (uint32_t)__cvta_generic_to_shared(smem_ptr);
    asm volatile("cp.async.cg.shared.global [%0], [%1], 16;" :: "r"(s), "l"(gptr));
}
#define CP_COMMIT() asm volatile("cp.async.commit_group;")
#define CP_WAIT0()  asm volatile("cp.async.wait_group 0;")
#define CP_WAIT1()  asm volatile("cp.async.wait_group 1;")

// ================= TF32 GEMM core (CTA 128x128, BK=32, 256 thr) =================
#define GBM 128
#define GBN 128
#define GBK 32
#define AS_STRIDE 36
#define BS_STRIDE 136
#define ABUF (GBM * AS_STRIDE)
#define BBUF (GBK * BS_STRIDE)
#define GEMM_SMEM_FLOATS (2 * (ABUF + BBUF))
#define GEMM_SMEM_BYTES  (GEMM_SMEM_FLOATS * 4)

#define A_ID(x)   (x)
#define A_TF32(x) to_tf32(x)

// mainloop producing acc[2][8][4]; ACVT/BCVT applied to fragments
#define GEMM_MAINLOOP(A, lda, B, N, K, m0, n0, ACVT, BCVT)                            \
    float acc[2][8][4];                                                               \
    _Pragma("unroll") for (int mi = 0; mi < 2; mi++)                                  \
    _Pragma("unroll") for (int ni = 0; ni < 8; ni++)                                  \
    _Pragma("unroll") for (int j = 0; j < 4; j++) acc[mi][ni][j] = 0.f;               \
    int nk = (K) / GBK;                                                               \
    auto load_tile = [&](int kt, int bufi) {                                          \
        float* As_ = sm + bufi * (ABUF + BBUF);                                       \
        float* Bs_ = As_ + ABUF;                                                      \
        int k0 = kt * GBK;                                                            \
        _Pragma("unroll") for (int p = 0; p < 4; p++) {                               \
            int idx = tid + p * 256;                                                  \
            int r = idx >> 3, c = (idx & 7) * 4;                                      \
            cp_async16(&As_[r * AS_STRIDE + c], (A) + (size_t)((m0) + r) * (lda) + k0 + c); \
        }                                                                             \
        _Pragma("unroll") for (int p = 0; p < 4; p++) {                               \
            int idx = tid + p * 256;                                                  \
            int r = idx >> 5, c = (idx & 31) * 4;                                     \
            cp_async16(&Bs_[r * BS_STRIDE + c], (B) + (size_t)(k0 + r) * (N) + (n0) + c); \
        }                                                                             \
        CP_COMMIT();                                                                  \
    };                                                                                \
    load_tile(0, 0);                                                                  \
    for (int kt = 0; kt < nk; kt++) {                                                 \
        int bufi = kt & 1;                                                            \
        if (kt + 1 < nk) { load_tile(kt + 1, bufi ^ 1); CP_WAIT1(); }                 \
        else            { CP_WAIT0(); }                                               \
        __syncthreads();                                                              \
        const float* As_ = sm + bufi * (ABUF + BBUF);                                 \
        const float* Bs_ = As_ + ABUF;                                                \
        _Pragma("unroll") for (int k8 = 0; k8 < 4; k8++) {                            \
            int kc = k8 * 8;                                                          \
            uint32_t a[2][4];                                                         \
            _Pragma("unroll") for (int mi = 0; mi < 2; mi++) {                        \
                int row = wm * 32 + mi * 16;                                          \
                a[mi][0] = __float_as_uint(ACVT(As_[(row + g) * AS_STRIDE + kc + t]));      \
                a[mi][1] = __float_as_uint(ACVT(As_[(row + g + 8) * AS_STRIDE + kc + t]));  \
                a[mi][2] = __float_as_uint(ACVT(As_[(row + g) * AS_STRIDE + kc + t + 4]));  \
                a[mi][3] = __float_as_uint(ACVT(As_[(row + g + 8) * AS_STRIDE + kc + t + 4])); \
            }                                                                         \
            _Pragma("unroll") for (int ni = 0; ni < 8; ni++) {                        \
                int col = wn * 64 + ni * 8 + g;                                       \
                uint32_t b0 = __float_as_uint(BCVT(Bs_[(kc + t) * BS_STRIDE + col]));       \
                uint32_t b1 = __float_as_uint(BCVT(Bs_[(kc + t + 4) * BS_STRIDE + col]));   \
                mma_tf32(acc[0][ni], a[0][0], a[0][1], a[0][2], a[0][3], b0, b1);     \
                mma_tf32(acc[1][ni], a[1][0], a[1][1], a[1][2], a[1][3], b0, b1);     \
            }                                                                         \
        }                                                                             \
        __syncthreads();                                                              \
    }

#define GEMM_PREAMBLE                  \
    extern __shared__ float sm[];      \
    int tid  = threadIdx.x;            \
    int wid  = tid >> 5;               \
    int lane = tid & 31;               \
    int wm = wid >> 1;                 \
    int wn = wid & 1;                  \
    int g  = lane >> 2;                \
    int t  = lane & 3;

// ================= fused precompute mega-kernel =================
// block ranges: [0,64) weff GEMM (inline cvt); [64, 64+RA) round x/w13/b13;
// next 768 wq (inline cvt); last 256 beff. All independent.
#define RW_X    1048576
#define RW_W13  (RW_X + 98304)
#define RW_TOT  (RW_W13 + 96)
#define MG_WEFF 64
#define MG_RA_BLK ((RW_TOT + 255) / 256)        // 4481
#define MG_RA_END (MG_WEFF + MG_RA_BLK)
#define MG_WQ_END (MG_RA_END + 768)
#define MG_TOTAL  (MG_WQ_END + 256)

__global__ __launch_bounds__(256, 2)
void mega_pre_kernel(const float* __restrict__ x,    float* __restrict__ ox,
                     const float* __restrict__ w1i,  const float* __restrict__ w3i,
                     float* __restrict__ w13o,
                     const float* __restrict__ b1i,  const float* __restrict__ b3i,
                     float* __restrict__ b13o,
                     const float* __restrict__ w2raw, const float* __restrict__ w4raw,
                     const float* __restrict__ w5raw,
                     const float* __restrict__ b2,
                     float* __restrict__ wqn, float* __restrict__ bqn,
                     const float* __restrict__ b45, const float* __restrict__ b_o,
                     float* __restrict__ weff, float* __restrict__ beff)
{
    int bid = blockIdx.x;
    if (bid < MG_WEFF) {
        // ---- W_eff_h = W_uv_h @ W_o_h (raw inputs, inline tf32 cvt) ----
        GEMM_PREAMBLE
        int h = bid >> 3;
        int n0 = (bid & 7) * GBN;
        int m0 = 0;
        const float* A = w4raw + 512 + h * 256;
        const float* B = w5raw + (size_t)h * 256 * 1024;
        GEMM_MAINLOOP(A, 2560, B, 1024, 256, m0, n0, A_TF32, A_TF32)
#pragma unroll
        for (int ni = 0; ni < 8; ni++) {
            int col = n0 + wn * 64 + ni * 8 + 2 * t;
#pragma unroll
            for (int mi = 0; mi < 2; mi++) {
                int r0 = h * 128 + wm * 32 + mi * 16 + g;
                float2 v0 = make_float2(to_tf32(acc[mi][ni][0]), to_tf32(acc[mi][ni][1]));
                float2 v1 = make_float2(to_tf32(acc[mi][ni][2]), to_tf32(acc[mi][ni][3]));
                *(float2*)(weff + (size_t)r0 * 1024 + col) = v0;
                *(float2*)(weff + (size_t)(r0 + 8) * 1024 + col) = v1;
            }
        }
    } else if (bid < MG_RA_END) {
        // ---- round x -> x32; pack w13/b13 ----
        int i = (bid - MG_WEFF) * 256 + threadIdx.x;
        if (i >= RW_TOT) return;
        float4 v;
        float4* dst;
        if (i < RW_X) {
            v = ((const float4*)x)[i];
            dst = (float4*)ox + i;
        } else if (i < RW_W13) {
            int o = i - RW_X;
            int k = o / 96, c4 = (o % 96) * 4;
            if (c4 < 128)      v = *(const float4*)(w1i + (size_t)k * 128 + c4);
            else if (c4 < 320) v = *(const float4*)(w3i + (size_t)k * 192 + (c4 - 128));
            else               v = make_float4(0.f, 0.f, 0.f, 0.f);
            dst = (float4*)w13o + o;
        } else {
            int o = i - RW_W13;
            int c4 = o * 4;
            if (c4 < 128)      v = *(const float4*)(b1i + c4);
            else if (c4 < 320) v = *(const float4*)(b3i + (c4 - 128));
            else               v = make_float4(0.f, 0.f, 0.f, 0.f);
            *(float4*)(b13o + c4) = v;
            return;
        }
        v.x = to_tf32(v.x); v.y = to_tf32(v.y);
        v.z = to_tf32(v.z); v.w = to_tf32(v.w);
        *dst = v;
    } else if (bid < MG_WQ_END) {
        // ---- absorbed q weights (raw inputs, inline cvt) ----
        int idx = (bid - MG_RA_END) * 256 + threadIdx.x;
        if (idx >= 128 * QN2) return;
        int r = idx / QN2;
        int c = idx % QN2;
        int h = c / KD2;
        int j = c - h * KD2;
        float val, bv = 0.f;
        if (j < 128) {
            float s = 0.f, bs = 0.f;
            const float* w2p = w2raw + (size_t)r * 1024 + h * 96;
            const float* w4p = w4raw + (size_t)j * 2560 + h * 64;
            const float* b2p = b2 + h * 96;
#pragma unroll 8
            for (int d = 0; d < 64; d++) {
                float w4v = to_tf32(w4p[d]);
                s  += to_tf32(w2p[d]) * w4v;
                bs += b2p[d] * w4v;
            }
            val = to_tf32(s);
            bv = bs;
        } else if (j < 160) {
            val = to_tf32(w2raw[(size_t)r * 1024 + h * 96 + 64 + (j - 128)]);
            bv  = b2[h * 96 + 64 + (j - 128)];
        } else {
            val = to_tf32(w2raw[(size_t)r * 1024 + 768 + h * 32 + (j - 160)]);
            bv  = b2[768 + h * 32 + (j - 160)];
        }
        wqn[(size_t)r * QN2 + c] = val;
        if (r == 0) bqn[c] = bv;
    } else {
        // ---- b_eff = b_o + b_v @ W_o ----
        __shared__ float red[256];
        int jb = (bid - MG_WQ_END) * 4;
        int tj = threadIdx.x & 3;
        int tr = threadIdx.x >> 2;
        int j = jb + tj;
        float s = 0.f;
        int r0 = tr * 32;
#pragma unroll 8
        for (int r = r0; r < r0 + 32; r++)
            s += b45[512 + r] * w5raw[(size_t)r * 1024 + j];
        red[threadIdx.x] = s;
        __syncthreads();
        if (threadIdx.x < 4) {
            float acc2 = b_o[jb + threadIdx.x];
#pragma unroll
            for (int k = 0; k < 64; k++) acc2 += red[k * 4 + threadIdx.x];
            beff[jb + threadIdx.x] = acc2;
        }
    }
}

// ---------------- plain GEMM + bias, fp32 out ----------------
__global__ __launch_bounds__(256, 2)
void gemm_tf32_kernel(const float* __restrict__ A, int lda,
                      const float* __restrict__ B,
                      const float* __restrict__ bias,
                      float* __restrict__ C,
                      int M, int N, int K)
{
    GEMM_PREAMBLE
    int m0 = blockIdx.y * GBM;
    int n0 = blockIdx.x * GBN;
    GEMM_MAINLOOP(A, lda, B, N, K, m0, n0, A_ID, A_ID)

#pragma unroll
    for (int ni = 0; ni < 8; ni++) {
        int col = n0 + wn * 64 + ni * 8 + 2 * t;
        float2 bv = *(const float2*)(bias + col);
#pragma unroll
        for (int mi = 0; mi < 2; mi++) {
            int r0 = m0 + wm * 32 + mi * 16 + g;
            float2 v0 = make_float2(acc[mi][ni][0] + bv.x, acc[mi][ni][1] + bv.y);
            float2 v1 = make_float2(acc[mi][ni][2] + bv.x, acc[mi][ni][3] + bv.y);
            *(float2*)(C + (size_t)r0 * N + col) = v0;
            *(float2*)(C + (size_t)(r0 + 8) * N + col) = v1;
        }
    }
}

// ---------------- cqkv GEMM (A = pre-rounded x32) ----------------
#define STG_STRIDE 129
__global__ __launch_bounds__(256, 2)
void gemm_cqkv_kernel(const float* __restrict__ A,
                      const float* __restrict__ B,
                      const float* __restrict__ bias,
                      const float* __restrict__ wq_norm,
                      const float* __restrict__ wkv_norm,
                      const int* __restrict__ pos,
                      float* __restrict__ cq,
                      float* __restrict__ ks)
{
    GEMM_PREAMBLE
    int m0 = blockIdx.y * GBM;
    int tileN = blockIdx.x;            // 0,1,2
    int n0 = tileN * GBN;
    GEMM_MAINLOOP(A, DIM_, B, CQKV_N, DIM_, m0, n0, A_ID, A_ID)

    if (tileN < 2) {
        float* stage = sm;
        float* scl   = sm + 128 * STG_STRIDE;
#pragma unroll
        for (int ni = 0; ni < 8; ni++) {
            int col = wn * 64 + ni * 8 + 2 * t;
            float2 bv = *(const float2*)(bias + n0 + col);
#pragma unroll
            for (int mi = 0; mi < 2; mi++) {
#pragma unroll
                for (int hf = 0; hf < 2; hf++) {
                    int rowl = wm * 32 + mi * 16 + g + hf * 8;
                    stage[rowl * STG_STRIDE + col]     = acc[mi][ni][hf * 2 + 0] + bv.x;
                    stage[rowl * STG_STRIDE + col + 1] = acc[mi][ni][hf * 2 + 1] + bv.y;
                }
            }
        }
        __syncthreads();
        if (tid < 128) {
            const float* rp = stage + tid * STG_STRIDE;
            float ssq = 0.f;
#pragma unroll 16
            for (int c = 0; c < 128; c++) ssq += rp[c] * rp[c];
            scl[tid] = rsqrtf(ssq * (1.f / 128.f) + 1e-8f);
        }
        __syncthreads();
        const float* w = (tileN == 0) ? wq_norm : wkv_norm;
        for (int idx = tid; idx < 128 * 128; idx += 256) {
            int row = idx >> 7, col = idx & 127;
            float v = to_tf32(stage[row * STG_STRIDE + col] * w[col] * scl[row]);
            if (tileN == 0) cq[(size_t)(m0 + row) * 128 + col] = v;
            else            ks[(size_t)(m0 + row) * KD2 + col] = v;
        }
    } else {
        if (wn == 0) {
#pragma unroll
            for (int ni = 0; ni < 8; ni++) {
                int col = ni * 8 + 2 * t;
                float2 bv = *(const float2*)(bias + n0 + col);
                int i = col >> 1;
                float inv = powf(10000.f, -(float)(2 * i) / 64.f);
#pragma unroll
                for (int mi = 0; mi < 2; mi++) {
#pragma unroll
                    for (int hf = 0; hf < 2; hf++) {
                        int row = m0 + wm * 32 + mi * 16 + g + hf * 8;
                        float xe = acc[mi][ni][hf * 2 + 0] + bv.x;
                        float xo = acc[mi][ni][hf * 2 + 1] + bv.y;
                        float ang = (float)pos[row] * inv;
                        float sn, cs;
                        sincosf(ang, &sn, &cs);
                        float* dst = ks + (size_t)row * KD2 + 128 + 2 * i;
                        dst[0] = to_tf32(xe * cs - xo * sn);
                        dst[1] = to_tf32(xe * sn + xo * cs);
                    }
                }
            }
        }
    }
}

// ---------------- absorbed q GEMM: qs[b,h,s,192] ----------------
__global__ __launch_bounds__(256, 2)
void gemm_qnew_kernel(const float* __restrict__ A,
                      const float* __restrict__ B,
                      const float* __restrict__ bias,
                      const int* __restrict__ pos,
                      float* __restrict__ qs)
{
    GEMM_PREAMBLE
    int m0 = blockIdx.y * GBM;
    int n0 = blockIdx.x * GBN;
    GEMM_MAINLOOP(A, 128, B, QN2, 128, m0, n0, A_ID, A_ID)

#pragma unroll
    for (int ni = 0; ni < 8; ni++) {
        int col = n0 + wn * 64 + ni * 8 + 2 * t;
        float2 bv = *(const float2*)(bias + col);
        int h = col / KD2;
        int j = col - h * KD2;
#pragma unroll
        for (int mi = 0; mi < 2; mi++) {
#pragma unroll
            for (int hf = 0; hf < 2; hf++) {
                int row = m0 + wm * 32 + mi * 16 + g + hf * 8;
                float c0 = acc[mi][ni][hf * 2 + 0] + bv.x;
                float c1 = acc[mi][ni][hf * 2 + 1] + bv.y;
                float o0, o1;
                if (j < 160) {
                    o0 = c0; o1 = c1;
                } else {
                    int i = (j - 160) >> 1;
                    float ang = (float)pos[row] * powf(10000.f, -(float)(2 * i) / 32.f);
                    float sn, cs;
                    sincosf(ang, &sn, &cs);
                    o0 = c0 * cs - c1 * sn;
                    o1 = c0 * sn + c1 * cs;
                }
                int b = row >> 11, s = row & 2047;
                float* dst = qs + (((size_t)(b * 8 + h) * 2048 + s) * KD2 + j);
                dst[0] = to_tf32(o0 * SM_SCALE);
                dst[1] = to_tf32(o1 * SM_SCALE);
            }
        }
    }
}

// ---------------- absorbed flash attention ----------------
#define QS_STRIDE 196
#define KS_STRIDE 196
#define VS_STRIDE 136
#define PS_STRIDE 68
#define QS_OFF  0
#define KS_OFF  (QS_OFF + 128 * QS_STRIDE)
#define VS_OFF  (KS_OFF + 64 * KS_STRIDE)
#define PS_OFF  (VS_OFF + 64 * VS_STRIDE)
#define STM_OFF (PS_OFF + 128 * PS_STRIDE)
#define STS_OFF (STM_OFF + 256)
#define FLASH_SMEM_FLOATS (STS_OFF + 256)
#define FLASH_SMEM_BYTES  (FLASH_SMEM_FLOATS * 4)
#define NKT (S_LEN / 64)

__global__ __launch_bounds__(512, 1)
void flash_mma_kernel(const float* __restrict__ qs, const float* __restrict__ ks,
                      float* __restrict__ attn)
{
    extern __shared__ float sm[];
    float* Qs  = sm + QS_OFF;
    float* Ks  = sm + KS_OFF;
    float* Vs  = sm + VS_OFF;
    float* Ps  = sm + PS_OFF;
    float* StM = sm + STM_OFF;
    float* StS = sm + STS_OFF;

    int b = blockIdx.z, h = blockIdx.y, qt = blockIdx.x;
    int tid  = threadIdx.x;
    int wid  = tid >> 5;
    int lane = tid & 31;
    int mw = wid >> 1;
    int nw = wid & 1;
    int g  = lane >> 2;
    int t  = lane & 3;

    size_t bh = (size_t)(b * NH + h) * S_LEN;
    const float* Kbase = ks + (size_t)b * S_LEN * KD2;

    auto load_k_tile = [&](int kt) {
        const float* Kg = Kbase + (size_t)kt * 64 * KD2;
#pragma unroll
        for (int p = 0; p < 6; p++) {
            int idx = tid + p * 512;
            int r = idx / 48, c = (idx % 48) * 4;
            cp_async16(&Ks[r * KS_STRIDE + c], Kg + r * KD2 + c);
        }
        CP_COMMIT();
    };
    auto load_v_tile = [&](int kt) {
        const float* Kg = Kbase + (size_t)kt * 64 * KD2;
#pragma unroll
        for (int p = 0; p < 4; p++) {
            int idx = tid + p * 512;
            int r = idx >> 5, c = (idx & 31) * 4;
            cp_async16(&Vs[r * VS_STRIDE + c], Kg + r * KD2 + c);
        }
        CP_COMMIT();
    };

    load_k_tile(0);
    {
        const float4* Qg = (const float4*)(qs + (bh + (size_t)qt * 128) * KD2);
#pragma unroll
        for (int p = 0; p < 12; p++) {
            int idx = tid + p * 512;
            int r = idx / 48, c4 = idx % 48;
            *(float4*)&Qs[r * QS_STRIDE + c4 * 4] = Qg[r * 48 + c4];
        }
    }

    int qrow = mw * 16;
    float m0 = -1e30f, m1 = -1e30f, l0 = 0.f, l1 = 0.f;
    float o[8][4];
#pragma unroll
    for (int dt = 0; dt < 8; dt++)
#pragma unroll
        for (int j = 0; j < 4; j++) o[dt][j] = 0.f;

    for (int kt = 0; kt < NKT; kt++) {
        CP_WAIT0();
        __syncthreads();

        load_v_tile(kt);

        float c[4][4];
#pragma unroll
        for (int nt = 0; nt < 4; nt++)
#pragma unroll
            for (int j = 0; j < 4; j++) c[nt][j] = 0.f;

#pragma unroll
        for (int k8 = 0; k8 < 24; k8++) {
            int kc = k8 * 8;
            uint32_t a0 = __float_as_uint(Qs[(qrow + g) * QS_STRIDE + kc + t]);
            uint32_t a1 = __float_as_uint(Qs[(qrow + g + 8) * QS_STRIDE + kc + t]);
            uint32_t a2 = __float_as_uint(Qs[(qrow + g) * QS_STRIDE + kc + t + 4]);
            uint32_t a3 = __float_as_uint(Qs[(qrow + g + 8) * QS_STRIDE + kc + t + 4]);
#pragma unroll
            for (int nt = 0; nt < 4; nt++) {
                int ncol = nw * 32 + nt * 8 + g;
                uint32_t b0 = __float_as_uint(Ks[ncol * KS_STRIDE + kc + t]);
                uint32_t b1 = __float_as_uint(Ks[ncol * KS_STRIDE + kc + t + 4]);
                mma_tf32(c[nt], a0, a1, a2, a3, b0, b1);
            }
        }

        float pm0 = -1e30f, pm1 = -1e30f;
#pragma unroll
        for (int nt = 0; nt < 4; nt++) {
            pm0 = fmaxf(pm0, fmaxf(c[nt][0], c[nt][1]));
            pm1 = fmaxf(pm1, fmaxf(c[nt][2], c[nt][3]));
        }
        pm0 = fmaxf(pm0, __shfl_xor_sync(0xffffffffu, pm0, 1));
        pm0 = fmaxf(pm0, __shfl_xor_sync(0xffffffffu, pm0, 2));
        pm1 = fmaxf(pm1, __shfl_xor_sync(0xffffffffu, pm1, 1));
        pm1 = fmaxf(pm1, __shfl_xor_sync(0xffffffffu, pm1, 2));

        float ex[4][4];
        float ps0 = 0.f, ps1 = 0.f;
#pragma unroll
        for (int nt = 0; nt < 4; nt++) {
            ex[nt][0] = __expf(c[nt][0] - pm0);
            ex[nt][1] = __expf(c[nt][1] - pm0);
            ex[nt][2] = __expf(c[nt][2] - pm1);
            ex[nt][3] = __expf(c[nt][3] - pm1);
            ps0 += ex[nt][0] + ex[nt][1];
            ps1 += ex[nt][2] + ex[nt][3];
        }
        ps0 += __shfl_xor_sync(0xffffffffu, ps0, 1);
        ps0 += __shfl_xor_sync(0xffffffffu, ps0, 2);
        ps1 += __shfl_xor_sync(0xffffffffu, ps1, 1);
        ps1 += __shfl_xor_sync(0xffffffffu, ps1, 2);

        if (t == 0) {
            StM[nw * 128 + qrow + g]     = pm0;
            StM[nw * 128 + qrow + g + 8] = pm1;
            StS[nw * 128 + qrow + g]     = ps0;
            StS[nw * 128 + qrow + g + 8] = ps1;
        }
        __syncthreads();

        if (kt + 1 < NKT) load_k_tile(kt + 1);

        int ow = 1 - nw;
        float pmO0 = StM[ow * 128 + qrow + g];
        float pmO1 = StM[ow * 128 + qrow + g + 8];
        float psO0 = StS[ow * 128 + qrow + g];
        float psO1 = StS[ow * 128 + qrow + g + 8];

        float mn0 = fmaxf(pm0, pmO0);
        float mn1 = fmaxf(pm1, pmO1);
        float rs0 = ps0 * __expf(pm0 - mn0) + psO0 * __expf(pmO0 - mn0);
        float rs1 = ps1 * __expf(pm1 - mn1) + psO1 * __expf(pmO1 - mn1);

        float mnew0 = fmaxf(m0, mn0);
        float mnew1 = fmaxf(m1, mn1);
        float corr0 = __expf(m0 - mnew0);
        float corr1 = __expf(m1 - mnew1);
        l0 = l0 * corr0 + rs0 * __expf(mn0 - mnew0);
        l1 = l1 * corr1 + rs1 * __expf(mn1 - mnew1);
        m0 = mnew0;
        m1 = mnew1;

#pragma unroll
        for (int dt = 0; dt < 8; dt++) {
            o[dt][0] *= corr0;
            o[dt][1] *= corr0;
            o[dt][2] *= corr1;
            o[dt][3] *= corr1;
        }

        float f0 = __expf(pm0 - mnew0);
        float f1 = __expf(pm1 - mnew1);
#pragma unroll
        for (int nt = 0; nt < 4; nt++) {
            int col = nw * 32 + nt * 8 + 2 * t;
            *(float2*)&Ps[(qrow + g) * PS_STRIDE + col] =
                make_float2(to_tf32(ex[nt][0] * f0), to_tf32(ex[nt][1] * f0));
            *(float2*)&Ps[(qrow + g + 8) * PS_STRIDE + col] =
                make_float2(to_tf32(ex[nt][2] * f1), to_tf32(ex[nt][3] * f1));
        }

        if (kt + 1 < NKT) { CP_WAIT1(); } else { CP_WAIT0(); }
        __syncthreads();

#pragma unroll
        for (int k8 = 0; k8 < 8; k8++) {
            int kc = k8 * 8;
            uint32_t a0 = __float_as_uint(Ps[(qrow + g) * PS_STRIDE + kc + t]);
            uint32_t a1 = __float_as_uint(Ps[(qrow + g + 8) * PS_STRIDE + kc + t]);
            uint32_t a2 = __float_as_uint(Ps[(qrow + g) * PS_STRIDE + kc + t + 4]);
            uint32_t a3 = __float_as_uint(Ps[(qrow + g + 8) * PS_STRIDE + kc + t + 4]);
#pragma unroll
            for (int dt = 0; dt < 8; dt++) {
                int dv = nw * 64 + dt * 8 + g;
                uint32_t b0 = __float_as_uint(Vs[(kc + t) * VS_STRIDE + dv]);
                uint32_t b1 = __float_as_uint(Vs[(kc + t + 4) * VS_STRIDE + dv]);
                mma_tf32(o[dt], a0, a1, a2, a3, b0, b1);
            }
        }
    }

    float inv0 = 1.f / l0;
    float inv1 = 1.f / l1;
    int row0 = b * S_LEN + qt * 128 + qrow + g;
    int row1 = row0 + 8;
#pragma unroll
    for (int dt = 0; dt < 8; dt++) {
        int col = h * 128 + nw * 64 + dt * 8 + 2 * t;
        float2 v0 = make_float2(to_tf32(o[dt][0] * inv0), to_tf32(o[dt][1] * inv0));
        float2 v1 = make_float2(to_tf32(o[dt][2] * inv1), to_tf32(o[dt][3] * inv1));
        *(float2*)(attn + (size_t)row0 * 1024 + col) = v0;
        *(float2*)(attn + (size_t)row1 * 1024 + col) = v1;
    }
}

// ---------------- host launcher ----------------
extern "C" void kernel_launch(void* const* d_in, const int* in_sizes, int n_in,
                              void* d_out, int out_size)
{
    const float* x         = (const float*)d_in[0];
    const int*   pos       = (const int*)  d_in[1];
    const float* w_dq_w    = (const float*)d_in[2];
    const float* w_dq_b    = (const float*)d_in[3];
    const float* q_norm_w  = (const float*)d_in[4];
    const float* w_uq_qr_w = (const float*)d_in[5];
    const float* w_uq_qr_b = (const float*)d_in[6];
    const float* w_dkv_kr_w= (const float*)d_in[7];
    const float* w_dkv_kr_b= (const float*)d_in[8];
    const float* kv_norm_w = (const float*)d_in[9];
    const float* w_uk_uv_w = (const float*)d_in[10];
    const float* w_uk_uv_b = (const float*)d_in[11];
    const float* w_o_w     = (const float*)d_in[12];
    const float* w_o_b     = (const float*)d_in[13];
    float* out = (float*)d_out;

    float *cq, *ksb, *qsb, *attn;
    float *x32, *w13, *b13, *wqn, *bqn, *weff, *beff;
    cudaGetSymbolAddress((void**)&cq,   g_cq);
    cudaGetSymbolAddress((void**)&ksb,  g_ks);
    cudaGetSymbolAddress((void**)&qsb,  g_qs);
    cudaGetSymbolAddress((void**)&attn, g_attn);
    cudaGetSymbolAddress((void**)&x32,  g_x32);
    cudaGetSymbolAddress((void**)&w13,  g_w13);
    cudaGetSymbolAddress((void**)&b13,  g_b13);
    cudaGetSymbolAddress((void**)&wqn,  g_wqn);
    cudaGetSymbolAddress((void**)&bqn,  g_bqn);
    cudaGetSymbolAddress((void**)&weff, g_weff);
    cudaGetSymbolAddress((void**)&beff, g_beff);

    cudaFuncSetAttribute(flash_mma_kernel, cudaFuncAttributeMaxDynamicSharedMemorySize,
                         FLASH_SMEM_BYTES);
    cudaFuncSetAttribute(gemm_tf32_kernel, cudaFuncAttributeMaxDynamicSharedMemorySize,
                         GEMM_SMEM_BYTES);
    cudaFuncSetAttribute(gemm_cqkv_kernel, cudaFuncAttributeMaxDynamicSharedMemorySize,
                         GEMM_SMEM_BYTES);
    cudaFuncSetAttribute(gemm_qnew_kernel, cudaFuncAttributeMaxDynamicSharedMemorySize,
                         GEMM_SMEM_BYTES);
    cudaFuncSetAttribute(mega_pre_kernel, cudaFuncAttributeMaxDynamicSharedMemorySize,
                         GEMM_SMEM_BYTES);

    dim3 blk(256);

    // one fused precompute launch: weff GEMM + rounding/packing + wq + beff
    mega_pre_kernel<<<MG_TOTAL, blk, GEMM_SMEM_BYTES>>>(
        x, x32, w_dq_w, w_dkv_kr_w, w13, w_dq_b, w_dkv_kr_b, b13,
        w_uq_qr_w, w_uk_uv_w, w_o_w, w_uq_qr_b, wqn, bqn,
        w_uk_uv_b, w_o_b, weff, beff);

    gemm_cqkv_kernel<<<dim3(3, NROWS / GBM), blk, GEMM_SMEM_BYTES>>>(
        x32, w13, b13, q_norm_w, kv_norm_w, pos, cq, ksb);

    gemm_qnew_kernel<<<dim3(QN2 / GBN, NROWS / GBM), blk, GEMM_SMEM_BYTES>>>(
        cq, wqn, bqn, pos, qsb);

    flash_mma_kernel<<<dim3(S_LEN / 128, NH, BATCH), 512, FLASH_SMEM_BYTES>>>(qsb, ksb, attn);

    gemm_tf32_kernel<<<dim3(1024 / GBN, NROWS / GBM), blk, GEMM_SMEM_BYTES>>>(
        attn, 1024, weff, beff, out, NROWS, 1024, 1024);
}